// round 14
// baseline (speedup 1.0000x reference)
#include <cuda_runtime.h>
#include <math.h>

// ---------------- problem constants ----------------
#define CB   32
#define CN   379
#define CH   512
#define CNH  8
#define CP   3
#define CWGH 4
#define CHD  64          // CH/CNH
#define CBN  (CB*CN)     // 12128
#define CBPN (CB*CP*CN)  // 36384
#define CNN  (CN*CN)     // 143641
#define KPAD 384         // pri K padded to multiple of 32

// padded per-stream row regions (multiples of 128)
#define M1P  12160       // 95*128  >= CBN
#define M2P  36480       // 285*128 >= CBPN
#define MGP  128         // >= CB*CP

#define X_SZ   (CBN*CH)          // 6209536
#define LOSS_OFF (2*X_SZ)
#define AWFC_OFF (LOSS_OFF+1)
#define AWSC_OFF (AWFC_OFF + CB*CP)

// gemm_tc dynamic smem: 2 stages x (128x36 + 32x136) words
#define GTC_SMEM ((2*128*36 + 2*32*136)*4)          // 71680 B
// k_attn dynamic smem: S 32x388 + Q 32x68 + Ts 32x76 + Vs 32x72
#define ATT_SMEM ((32*388 + 32*68 + 32*76 + 32*72)*4)   // 77312 B

// ---------------- static scratch (two-stream padded layouts) ----------------
static __device__ float g_z[2*M1P*CH];
static __device__ float g_qkv[(long long)2*M1P*3*CH];
static __device__ float g_pe[(long long)2*M2P*CH];
static __device__ float g_h[(long long)2*M2P*CH];
static __device__ float g_zc[2*M1P*CH];
static __device__ float g_fn[2*M1P*CH];
static __device__ float g_attnout[2*M1P*CH];
static __device__ float g_ffnh[(long long)2*M1P*4*CH];
static __device__ float g_proj[(long long)2*M1P*CH];
static __device__ float g_pri_pad[(long long)2*M2P*KPAD];
static __device__ float g_pw_pad[KPAD*CH];
static __device__ float g_gbar[2*MGP*CH];
static __device__ float g_gpart[2*CB*CP*8*CH];
static __device__ float g_tokens[2*MGP*CH];
static __device__ float g_qkvwg[2*MGP*3*CH];
static __device__ float g_dotp[2*CB*CP*8], g_psqp[2*CB*CP*8], g_pabsp[2*CB*CP*8];
static __device__ float g_csqp[2*CB*8];
static __device__ float g_sw[2*CB*CP], g_invmass[2*CB*CP], g_msum[2*CB];
static __device__ double g_kl[2];

__device__ __forceinline__ unsigned to_tf32(float v)
{
    unsigned r; asm("cvt.rna.tf32.f32 %0, %1;" : "=r"(r) : "f"(v)); return r;
}

__device__ __forceinline__ void mma8(float* c, unsigned a0, unsigned a1,
                                     unsigned a2, unsigned a3,
                                     unsigned b0, unsigned b1)
{
    asm volatile(
        "mma.sync.aligned.m16n8k8.row.col.f32.tf32.tf32.f32 "
        "{%0,%1,%2,%3}, {%4,%5,%6,%7}, {%8,%9}, {%0,%1,%2,%3};"
        : "+f"(c[0]), "+f"(c[1]), "+f"(c[2]), "+f"(c[3])
        : "r"(a0), "r"(a1), "r"(a2), "r"(a3), "r"(b0), "r"(b1));
}

// ---------------- tf32 tensor-core GEMM, dual-stream weight select -----------------
// Block tile 128x128, 256 threads = 8 warps (2m x 4n), warp tile 64x32,
// 2-stage cp.async, k-chunk 32, SINGLE barrier per chunk (safe: the barrier sits
// between compute(c-1) and issue(c+1); issue targets the buffer compute(c-1) read,
// and passing the barrier proves all warps finished compute(c-1)).
// REQUIRES K%32==0 and M multiple of 128.
// resMode: 0 none;
//          2: res[(st*M1P + b*CN + n)*Nc + gn] with gm-st*M2P=(b*CP+p)*CN+n (skip pads);
//          3: res=attnout (padded, gm*Nc); C=compact out row st*CBN+r_in (skip pads);
//             proj[gm*Nc+gn] = xn - dwp[st]*res.
__global__ void __launch_bounds__(256,2)
gemm_tc(const float* __restrict__ A,
        const float* __restrict__ W0, const float* __restrict__ W1,
        const float* __restrict__ b0, const float* __restrict__ b1,
        float* __restrict__ C,
        int M, int K, int Nc, int gridNx, int mSplit,
        const float* __restrict__ res, int resMode, int act,
        float* __restrict__ proj, const float* __restrict__ dwp)
{
    extern __shared__ unsigned char s_raw[];
    unsigned (*As)[128][36] = (unsigned (*)[128][36])s_raw;
    unsigned (*Ws)[32][136] = (unsigned (*)[32][136])(s_raw + 2*128*36*4);

    const int t    = threadIdx.x;        // 0..255
    const int bx   = blockIdx.x % gridNx;
    const int by   = blockIdx.x / gridNx;
    const int m0   = by * 128;
    const int n0   = bx * 128;
    const int st   = (m0 >= mSplit) ? 1 : 0;
    const float* W    = st ? W1 : W0;
    const float* bias = st ? b1 : b0;

    const int lane = t & 31, warp = t >> 5;
    const int wm   = warp >> 2;          // 0..1
    const int wn   = warp & 3;           // 0..3
    const int gid  = lane >> 2;          // 0..7
    const int tid4 = lane & 3;           // 0..3

    const int ac4 = t & 7;
    const int ar0 = t >> 3;              // 0..31
    const int wc4 = t & 31;
    const int wr0 = t >> 5;              // 0..7

    const float wv = (resMode == 3) ? dwp[st] : 0.f;

    float c[4][4][4];
    #pragma unroll
    for (int i=0;i<4;i++)
        #pragma unroll
        for (int j=0;j<4;j++)
            #pragma unroll
            for (int k=0;k<4;k++) c[i][j][k]=0.f;

    auto do_chunk = [&](const unsigned (*Ab)[36], const unsigned (*Wb)[136]) {
        #pragma unroll
        for (int k8 = 0; k8 < 32; k8 += 8) {
            unsigned a[4][4], b[4][2];
            #pragma unroll
            for (int ma = 0; ma < 4; ma++) {
                int rb = wm*64 + ma*16;
                a[ma][0] = Ab[rb + gid    ][k8 + tid4    ];
                a[ma][1] = Ab[rb + gid + 8][k8 + tid4    ];
                a[ma][2] = Ab[rb + gid    ][k8 + tid4 + 4];
                a[ma][3] = Ab[rb + gid + 8][k8 + tid4 + 4];
            }
            #pragma unroll
            for (int nb = 0; nb < 4; nb++) {
                int cn = wn*32 + nb*8 + gid;
                b[nb][0] = Wb[k8 + tid4    ][cn];
                b[nb][1] = Wb[k8 + tid4 + 4][cn];
            }
            #pragma unroll
            for (int ma = 0; ma < 4; ma++)
                #pragma unroll
                for (int nb = 0; nb < 4; nb++)
                    mma8(c[ma][nb], a[ma][0], a[ma][1], a[ma][2], a[ma][3],
                         b[nb][0], b[nb][1]);
        }
    };

    auto issue = [&](int kk, int buf) {
        #pragma unroll
        for (int v = 0; v < 4; v++) {            // A: 128x32
            int row = ar0 + 32*v;
            int gm  = m0 + row;
            const float* src = A + (long long)gm*K + kk + ac4*4;
            unsigned dst = (unsigned)__cvta_generic_to_shared(&As[buf][row][ac4*4]);
            asm volatile("cp.async.ca.shared.global [%0], [%1], 16, 16;"
                         :: "r"(dst), "l"(src));
        }
        #pragma unroll
        for (int v = 0; v < 4; v++) {            // W: 32x128
            int row = wr0 + 8*v;
            int gk  = kk + row;
            const float* src = W + (long long)gk*Nc + n0 + wc4*4;
            unsigned dst = (unsigned)__cvta_generic_to_shared(&Ws[buf][row][wc4*4]);
            asm volatile("cp.async.ca.shared.global [%0], [%1], 16, 16;"
                         :: "r"(dst), "l"(src));
        }
        asm volatile("cp.async.commit_group;");
    };

    int nb = K >> 5;
    issue(0, 0);
    int cur = 0;
    for (int cidx = 0; cidx < nb; cidx++) {
        asm volatile("cp.async.wait_group 0;" ::: "memory");
        __syncthreads();                       // single barrier per chunk
        if (cidx + 1 < nb) issue((cidx+1) << 5, cur ^ 1);
        do_chunk(As[cur], Ws[cur]);
        cur ^= 1;
    }

    // ---- epilogue ----
    #pragma unroll
    for (int ma = 0; ma < 4; ma++) {
        #pragma unroll
        for (int rr = 0; rr < 2; rr++) {
            int gm = m0 + wm*64 + ma*16 + gid + rr*8;
            long long resBase = -1;
            int outRow = -1;
            if (resMode == 2) {
                int g2 = gm - st*M2P;
                if (g2 < CBPN) {
                    int bb = g2 / (CP * CN);
                    int nn = g2 % CN;
                    resBase = ((long long)(st*M1P + bb*CN + nn)) * Nc;
                }
            } else if (resMode == 3) {
                resBase = (long long)gm * Nc;
                int r_in = gm - st*mSplit;
                if (r_in < CBN) outRow = st*CBN + r_in;
            }
            if (resMode == 2 && resBase < 0) continue;  // pad row: skip
            #pragma unroll
            for (int nb2 = 0; nb2 < 4; nb2++) {
                #pragma unroll
                for (int cc = 0; cc < 2; cc++) {
                    int gn = n0 + wn*32 + nb2*8 + 2*tid4 + cc;
                    float v = c[ma][nb2][rr*2 + cc];
                    if (bias) v += bias[gn];
                    if (resMode == 3) {
                        float r = res[resBase + gn];
                        float xn = v + r;
                        if (outRow >= 0) C[(long long)outRow * Nc + gn] = xn;
                        proj[(long long)gm * Nc + gn] = xn - wv*r;
                        continue;
                    }
                    if (resMode == 2) v += res[resBase + gn];
                    if (act) v = 0.5f * v * (1.f + erff(v * 0.70710678118654752f));
                    C[(long long)gm * Nc + gn] = v;
                }
            }
        }
    }
}

// ---------------- prescale priors (both streams) ----------------
__global__ void k_prescale(const float* __restrict__ pri0, const float* __restrict__ pri1)
{
    long long idx = (long long)blockIdx.x*blockDim.x + threadIdx.x;
    if (idx >= (long long)2*CBPN*KPAD) return;
    int s = (int)(idx / ((long long)CBPN*KPAD));
    long long rem = idx - (long long)s*CBPN*KPAD;
    int k = (int)(rem % KPAD);
    long long rowc = rem / KPAD;
    const float* pri = s ? pri1 : pri0;
    float v = 0.f;
    if (k < CN) v = pri[rowc*CN + k] * g_invmass[s*CB*CP + (int)(rowc / CN)];
    g_pri_pad[((long long)s*M2P + rowc)*KPAD + k] = __uint_as_float(to_tf32(v));
}

__global__ void k_prep_pw(const float* __restrict__ pw)
{
    int idx = blockIdx.x*blockDim.x + threadIdx.x;
    if (idx >= KPAD*CH) return;
    int r = idx / CH, c = idx % CH;
    float v = (r < CN) ? pw[r*CH + c] : 0.f;
    g_pw_pad[idx] = __uint_as_float(to_tf32(v));
}

// ---------------- fused attention (tensor-core QK^T and PV; inline mask) -----------
__global__ void __launch_bounds__(256) k_attn(const float* __restrict__ x0,
                                              const float* __restrict__ x1,
                                              const float* __restrict__ conn0,
                                              const float* __restrict__ conn1,
                                              const float* __restrict__ alpha)
{
    extern __shared__ unsigned char s_raw[];
    float (*S)[388]  = (float (*)[388])s_raw;
    float (*Qs)[68]  = (float (*)[68])(s_raw + 32*388*4);
    float (*Ts)[76]  = (float (*)[76])(s_raw + (32*388 + 32*68)*4);
    float (*Vs)[72]  = (float (*)[72])(s_raw + (32*388 + 32*68 + 32*76)*4);

    int blk = blockIdx.x;            // 2*CB*CNH*12
    int s = blk / (CB*96);
    int rem = blk % (CB*96);
    int b = rem / 96;
    int r2 = rem % 96;
    int h = r2 / 12;
    int i0 = (r2 % 12) * 32;
    int t = threadIdx.x;
    const float* x    = s ? x1 : x0;
    const float* conn = s ? conn1 : conn0;
    const long long qbase = (long long)s*M1P + (long long)b*CN;

    const int lane = t & 31, warp = t >> 5;
    const int wm   = warp >> 2;      // 0..1
    const int wn   = warp & 3;       // 0..3
    const int gid  = lane >> 2;      // 0..7
    const int tid4 = lane & 3;       // 0..3
    const int ldr  = t >> 3;         // 0..31 loader row
    const int ldc  = (t & 7) * 8;    // loader col base

    // load Q tile 32x64
    {
        int gi = i0 + ldr;
        const float* src = g_qkv + (qbase + (gi < CN ? gi : 0))*3*CH + h*CHD + ldc;
        #pragma unroll
        for (int u = 0; u < 8; u++) Qs[ldr][ldc+u] = (gi < CN) ? src[u] : 0.f;
    }
    __syncthreads();

    // ---- phase 1: S = Q K^T ----
    for (int j0 = 0; j0 < KPAD; j0 += 32) {
        {
            int gj = j0 + ldr;
            const float* src = g_qkv + (qbase + (gj < CN ? gj : 0))*3*CH + CH + h*CHD + ldc;
            #pragma unroll
            for (int u = 0; u < 8; u++) Ts[ldr][ldc+u] = (gj < CN) ? src[u] : 0.f;
        }
        __syncthreads();
        float c4[4] = {0.f,0.f,0.f,0.f};
        #pragma unroll
        for (int k8 = 0; k8 < 64; k8 += 8) {
            unsigned a0 = __float_as_uint(Qs[wm*16+gid  ][k8+tid4  ]);
            unsigned a1 = __float_as_uint(Qs[wm*16+gid+8][k8+tid4  ]);
            unsigned a2 = __float_as_uint(Qs[wm*16+gid  ][k8+tid4+4]);
            unsigned a3 = __float_as_uint(Qs[wm*16+gid+8][k8+tid4+4]);
            unsigned b0 = __float_as_uint(Ts[wn*8+gid][k8+tid4  ]);
            unsigned b1 = __float_as_uint(Ts[wn*8+gid][k8+tid4+4]);
            mma8(c4, a0, a1, a2, a3, b0, b1);
        }
        int col = j0 + wn*8 + 2*tid4;
        S[wm*16+gid  ][col  ] = c4[0];
        S[wm*16+gid  ][col+1] = c4[1];
        S[wm*16+gid+8][col  ] = c4[2];
        S[wm*16+gid+8][col+1] = c4[3];
        __syncthreads();
    }

    // ---- phase 2: inline mask + scale + row softmax (warp w: rows 4w..4w+3) ----
    {
        float a2c  = alpha[0]*0.5f;
        float base = a2c * g_msum[s*CB + b];
        float om   = 1.f - a2c;
        for (int rr = 0; rr < 4; rr++) {
            int i = warp*4 + rr;
            int gi = i0 + i;
            if (gi >= CN) continue;
            const float* crow = conn + (long long)gi*CN + (long long)b*CNN;
            float mx = -1e30f;
            for (int jc = lane; jc < CN; jc += 32) {
                float m = tanhf(base + om*crow[jc]);
                float v = 0.125f * S[i][jc] * (1.f + m);
                S[i][jc] = v;
                mx = fmaxf(mx, v);
            }
            #pragma unroll
            for (int o = 16; o > 0; o >>= 1) mx = fmaxf(mx, __shfl_xor_sync(~0u, mx, o));
            float sum = 0.f;
            for (int jc = lane; jc < CN; jc += 32) {
                float e = expf(S[i][jc] - mx);
                S[i][jc] = e;
                sum += e;
            }
            #pragma unroll
            for (int o = 16; o > 0; o >>= 1) sum += __shfl_xor_sync(~0u, sum, o);
            float inv = 1.f / sum;
            for (int jc = lane; jc < CN; jc += 32) S[i][jc] *= inv;
            for (int jc = CN + lane; jc < KPAD; jc += 32) S[i][jc] = 0.f;
        }
    }

    // ---- phase 3: ctx = P @ V ----
    float acc[2][4] = {};
    for (int j0 = 0; j0 < KPAD; j0 += 32) {
        __syncthreads();
        {
            int gj = j0 + ldr;
            const float* src = g_qkv + (qbase + (gj < CN ? gj : 0))*3*CH + 2*CH + h*CHD + ldc;
            #pragma unroll
            for (int u = 0; u < 8; u++) Vs[ldr][ldc+u] = (gj < CN) ? src[u] : 0.f;
        }
        __syncthreads();
        #pragma unroll
        for (int k8 = 0; k8 < 32; k8 += 8) {
            unsigned a0 = __float_as_uint(S[wm*16+gid  ][j0+k8+tid4  ]);
            unsigned a1 = __float_as_uint(S[wm*16+gid+8][j0+k8+tid4  ]);
            unsigned a2 = __float_as_uint(S[wm*16+gid  ][j0+k8+tid4+4]);
            unsigned a3 = __float_as_uint(S[wm*16+gid+8][j0+k8+tid4+4]);
            #pragma unroll
            for (int nt = 0; nt < 2; nt++) {
                int cn = wn*16 + nt*8 + gid;
                unsigned b0 = __float_as_uint(Vs[k8+tid4  ][cn]);
                unsigned b1 = __float_as_uint(Vs[k8+tid4+4][cn]);
                mma8(acc[nt], a0, a1, a2, a3, b0, b1);
            }
        }
    }
    // write: attnout = x + ctx + fn
    #pragma unroll
    for (int nt = 0; nt < 2; nt++) {
        #pragma unroll
        for (int rr = 0; rr < 2; rr++) {
            int gi = i0 + wm*16 + gid + rr*8;
            if (gi >= CN) continue;
            #pragma unroll
            for (int cc = 0; cc < 2; cc++) {
                int d = h*CHD + wn*16 + nt*8 + 2*tid4 + cc;
                long long oc = ((long long)(b*CN + gi))*CH + d;   // compact (x)
                long long op = (qbase + gi)*CH + d;                // padded
                g_attnout[op] = x[oc] + g_fn[op] + acc[nt][rr*2 + cc];
            }
        }
    }
}

// ---------------- layernorm (both streams; optional padded input) ----------------
__global__ void k_layernorm(const float* __restrict__ x0, const float* __restrict__ x1,
                            int inPadded, const float* __restrict__ g,
                            const float* __restrict__ b, int gRow0, float* __restrict__ z)
{
    int row = blockIdx.x;                 // 0..2*CBN-1
    int s = row >= CBN;
    int rin = row - s*CBN;
    const float* xr;
    if (inPadded) xr = x0 + ((long long)s*M1P + rin)*CH;
    else          xr = (s ? x1 : x0) + (long long)rin*CH;
    float* zr = z + ((long long)s*M1P + rin)*CH;
    const float* gp = g + (gRow0 + s)*CH;
    const float* bp = b + (gRow0 + s)*CH;
    __shared__ float red[256];
    int t = threadIdx.x;
    float v0 = xr[t], v1 = xr[t+256];
    red[t] = v0+v1; __syncthreads();
    for (int o=128;o>0;o>>=1){ if(t<o) red[t]+=red[t+o]; __syncthreads(); }
    float mean = red[0]*(1.f/CH); __syncthreads();
    float d0=v0-mean, d1=v1-mean;
    red[t]=d0*d0+d1*d1; __syncthreads();
    for (int o=128;o>0;o>>=1){ if(t<o) red[t]+=red[t+o]; __syncthreads(); }
    float rstd = rsqrtf(red[0]*(1.f/CH) + 1e-5f);
    zr[t]     = d0*rstd*gp[t]     + bp[t];
    zr[t+256] = d1*rstd*gp[t+256] + bp[t+256];
}

// ---------------- prior reductions (both streams) ----------------
__global__ void k_prior_part(const float* __restrict__ pri0, const float* __restrict__ pri1,
                             const float* __restrict__ conn0, const float* __restrict__ conn1)
{
    int blk = blockIdx.x;           // 2*CB*CP*8
    int s = blk / (CB*CP*8);
    int rem = blk % (CB*CP*8);
    int bp = rem >> 3, ch = rem & 7;
    int b = bp / CP;
    const float* pri  = s ? pri1  : pri0;
    const float* conn = s ? conn1 : conn0;
    const int CHK = (CNN + 7) / 8;
    int lo = ch*CHK, hi = lo + CHK; if (hi > CNN) hi = CNN;
    const float* p = pri  + (long long)bp*CNN;
    const float* c = conn + (long long)b*CNN;
    float dot=0, sq=0, ab=0;
    for (int i = lo + threadIdx.x; i < hi; i += blockDim.x) {
        float pv = p[i];
        dot += pv*c[i]; sq += pv*pv; ab += fabsf(pv);
    }
    __shared__ float r1[256], r2[256], r3[256];
    int t=threadIdx.x; r1[t]=dot;r2[t]=sq;r3[t]=ab; __syncthreads();
    for(int o=128;o>0;o>>=1){ if(t<o){r1[t]+=r1[t+o];r2[t]+=r2[t+o];r3[t]+=r3[t+o];} __syncthreads(); }
    if(t==0){ g_dotp[blk]=r1[0]; g_psqp[blk]=r2[0]; g_pabsp[blk]=r3[0]; }
}

__global__ void k_conn_part(const float* __restrict__ conn0, const float* __restrict__ conn1)
{
    int blk = blockIdx.x;           // 2*CB*8
    int s = blk / (CB*8);
    int rem = blk % (CB*8);
    int b = rem >> 3, ch = rem & 7;
    const float* conn = s ? conn1 : conn0;
    const int CHK = (CNN + 7) / 8;
    int lo = ch*CHK, hi = lo + CHK; if (hi > CNN) hi = CNN;
    const float* c = conn + (long long)b*CNN;
    float sq=0;
    for (int i = lo + threadIdx.x; i < hi; i += blockDim.x) { float v=c[i]; sq += v*v; }
    __shared__ float r[256];
    int t=threadIdx.x; r[t]=sq; __syncthreads();
    for(int o=128;o>0;o>>=1){ if(t<o) r[t]+=r[t+o]; __syncthreads(); }
    if(t==0) g_csqp[blk]=r[0];
}

__global__ void k_sw()
{
    if (threadIdx.x) return;
    int gb = blockIdx.x;            // 0..2*CB-1
    float csq=0;
    #pragma unroll
    for (int u=0;u<8;u++) csq += g_csqp[gb*8+u];
    float cn = fmaxf(sqrtf(csq), 1e-12f);
    float s[CP], mx=-1e30f;
    for (int p=0;p<CP;p++){
        int bp = gb*CP+p;
        float dot=0, sq=0, ab=0;
        #pragma unroll
        for (int u=0;u<8;u++){ dot+=g_dotp[bp*8+u]; sq+=g_psqp[bp*8+u]; ab+=g_pabsp[bp*8+u]; }
        float pn = fmaxf(sqrtf(sq), 1e-12f);
        s[p] = dot/(cn*pn);
        mx = fmaxf(mx, s[p]);
        g_invmass[bp] = 1.f/ab;
    }
    float sum=0;
    for (int p=0;p<CP;p++){ s[p]=expf(s[p]-mx); sum+=s[p]; }
    for (int p=0;p<CP;p++) g_sw[gb*CP+p]=s[p]/sum;
}

// ---------------- fused_nh (both streams) ----------------
__global__ void k_fused_nh()
{
    long long idx = (long long)blockIdx.x*blockDim.x + threadIdx.x;
    if (idx >= (long long)2*CBN*CH) return;
    int s = (int)(idx / X_SZ);
    long long rem = idx - (long long)s*X_SZ;
    int c = (int)(rem % CH);
    long long bn = rem / CH;
    int b = (int)(bn / CN), n = (int)(bn % CN);
    float acc=0;
    #pragma unroll
    for (int p=0;p<CP;p++)
        acc += g_sw[(s*CB+b)*CP+p] *
               g_pe[((long long)s*M2P + (long long)(b*CP+p)*CN + n)*CH + c];
    g_fn[((long long)s*M1P + bn)*CH + c] = acc;
}

// ---------------- gbar two-stage (both streams) ----------------
__global__ void k_gbar_part()
{
    int blk = blockIdx.x;           // 2*CB*CP*8
    int s = blk / (CB*CP*8);
    int rem = blk % (CB*CP*8);
    int bp = rem >> 3, ch = rem & 7;
    int c = threadIdx.x;
    int nlo = ch*48, nhi = nlo+48; if (nhi > CN) nhi = CN;
    float a0=0, a1=0;
    for (int n=nlo; n<nhi; n++){
        const float* r = g_h + ((long long)s*M2P + (long long)bp*CN + n)*CH;
        a0 += r[c]; a1 += r[c+256];
    }
    g_gpart[(long long)blk*CH + c]       = a0;
    g_gpart[(long long)blk*CH + c + 256] = a1;
}

__global__ void k_gbar_fin()
{
    int gbp = blockIdx.x;           // 2*CB*CP
    int s = gbp / (CB*CP);
    int bp = gbp % (CB*CP);
    int c = threadIdx.x;
    float a0=0, a1=0;
    #pragma unroll
    for (int ch=0; ch<8; ch++){
        const float* r = g_gpart + (long long)(gbp*8+ch)*CH;
        a0 += r[c]; a1 += r[c+256];
    }
    g_gbar[(s*MGP+bp)*CH+c]     = a0*(1.f/CN);
    g_gbar[(s*MGP+bp)*CH+c+256] = a1*(1.f/CN);
}

// ---------------- tiny weight-gen MHA (both streams) ----------------
__global__ void k_wg_attn(float* __restrict__ out)
{
    int gb = blockIdx.x;            // 0..2*CB-1
    int s = gb / CB;
    int b = gb % CB;
    __shared__ float logit[CWGH*CP*CP];
    int t = threadIdx.x;            // 64 threads
    if (t < CWGH*CP*CP) {
        int h = t/(CP*CP); int i = (t/CP)%CP; int j = t%CP;
        const float* q = g_qkvwg + (long long)(s*MGP + b*CP+i)*3*CH + h*128;
        const float* k = g_qkvwg + (long long)(s*MGP + b*CP+j)*3*CH + CH + h*128;
        float d=0;
        for (int x=0;x<128;x++) d += q[x]*k[x];
        logit[t] = d*0.08838834764831845f;   // 1/sqrt(128)
    }
    __syncthreads();
    if (t==0) {
        float aw[CP]={0,0,0};
        for (int h=0;h<CWGH;h++) for (int i=0;i<CP;i++) {
            float mx=-1e30f;
            for (int j=0;j<CP;j++) mx=fmaxf(mx, logit[(h*CP+i)*CP+j]);
            float e[CP], ss=0;
            for (int j=0;j<CP;j++){ e[j]=expf(logit[(h*CP+i)*CP+j]-mx); ss+=e[j]; }
            for (int j=0;j<CP;j++) aw[j]+= e[j]/ss;
        }
        for (int j=0;j<CP;j++) aw[j] *= (1.f/(CWGH*CP));
        float mx=-1e30f;
        for (int j=0;j<CP;j++) mx=fmaxf(mx, aw[j]);
        float ss=0, e[CP];
        for (int j=0;j<CP;j++){ e[j]=expf((aw[j]-mx)*100.f); ss+=e[j]; }  // temp 0.01
        float msum=0;
        float* awp = out + (s ? AWSC_OFF : AWFC_OFF) + b*CP;
        for (int j=0;j<CP;j++){ float a=e[j]/ss; awp[j]=a; msum+=a; }
        g_msum[gb]=msum;
    }
}

// ---------------- fused logsoftmax + KL (per row-pair) ----------------
__global__ void k_loss_all()
{
    int r = blockIdx.x;             // 0..CBN-1
    const float* p0 = g_proj + (long long)r*CH;
    const float* p1 = g_proj + ((long long)M1P + r)*CH;
    __shared__ float red[256];
    __shared__ double d1[256], d2[256];
    int t = threadIdx.x;
    float a0 = p0[t], b0 = p0[t+256];
    float a1 = p1[t], b1 = p1[t+256];

    // lse0
    red[t] = fmaxf(a0,b0); __syncthreads();
    for (int o=128;o>0;o>>=1){ if(t<o) red[t]=fmaxf(red[t],red[t+o]); __syncthreads(); }
    float mx0 = red[0]; __syncthreads();
    red[t] = expf(a0-mx0)+expf(b0-mx0); __syncthreads();
    for (int o=128;o>0;o>>=1){ if(t<o) red[t]+=red[t+o]; __syncthreads(); }
    float lse0 = logf(red[0]) + mx0; __syncthreads();
    // lse1
    red[t] = fmaxf(a1,b1); __syncthreads();
    for (int o=128;o>0;o>>=1){ if(t<o) red[t]=fmaxf(red[t],red[t+o]); __syncthreads(); }
    float mx1 = red[0]; __syncthreads();
    red[t] = expf(a1-mx1)+expf(b1-mx1); __syncthreads();
    for (int o=128;o>0;o>>=1){ if(t<o) red[t]+=red[t+o]; __syncthreads(); }
    float lse1 = logf(red[0]) + mx1; __syncthreads();

    float lf0 = a0 - lse0, lf1 = b0 - lse0;
    float ls0 = a1 - lse1, ls1 = b1 - lse1;
    d1[t] = (double)(expf(ls0)*(ls0-lf0)) + (double)(expf(ls1)*(ls1-lf1));
    d2[t] = (double)(expf(lf0)*(lf0-ls0)) + (double)(expf(lf1)*(lf1-ls1));
    __syncthreads();
    for (int o=128;o>0;o>>=1){ if(t<o){ d1[t]+=d1[t+o]; d2[t]+=d2[t+o]; } __syncthreads(); }
    if (t==0){ atomicAdd(&g_kl[0], d1[0]); atomicAdd(&g_kl[1], d2[0]); }
}

__global__ void k_zero_kl(){ g_kl[0]=0.0; g_kl[1]=0.0; }

__global__ void k_loss(float* __restrict__ out)
{
    out[0] = (float)(0.5*(g_kl[0]+g_kl[1])/(double)CBN);
}

// ---------------- host orchestration ----------------
// CRITICAL: __device__ symbols passed as kernel ARGUMENTS must be resolved via
// cudaGetSymbolAddress (host shadow address + GB300 ATS silently reads host RAM).
static float* sym_addr(const void* symbol)
{
    void* p = nullptr;
    cudaGetSymbolAddress(&p, symbol);
    return (float*)p;
}

extern "C" void kernel_launch(void* const* d_in, const int* in_sizes, int n_in,
                              void* d_out, int out_size)
{
    const float* x0      = (const float*)d_in[0];
    const float* x1      = (const float*)d_in[1];
    const float* pri0    = (const float*)d_in[2];
    const float* pri1    = (const float*)d_in[3];
    const float* conn0   = (const float*)d_in[4];
    const float* conn1   = (const float*)d_in[5];
    const float* dw      = (const float*)d_in[6];
    const float* wqkv0   = (const float*)d_in[7];
    const float* wqkv1   = (const float*)d_in[8];
    const float* ln_g    = (const float*)d_in[9];
    const float* ln_b    = (const float*)d_in[10];
    const float* ffn_w1  = (const float*)d_in[11];
    const float* ffn_b1  = (const float*)d_in[12];
    const float* ffn_w2  = (const float*)d_in[13];
    const float* ffn_b2  = (const float*)d_in[14];
    const float* pw      = (const float*)d_in[15];
    const float* pb      = (const float*)d_in[16];
    const float* f1w     = (const float*)d_in[17];
    const float* f1b     = (const float*)d_in[18];
    const float* f2w     = (const float*)d_in[19];
    const float* f2b     = (const float*)d_in[20];
    const float* ipw     = (const float*)d_in[21];
    const float* ipb     = (const float*)d_in[22];
    const float* alpha   = (const float*)d_in[23];
    float* out = (float*)d_out;

    float* p_z       = sym_addr(g_z);
    float* p_qkv     = sym_addr(g_qkv);
    float* p_pe      = sym_addr(g_pe);
    float* p_h       = sym_addr(g_h);
    float* p_zc      = sym_addr(g_zc);
    float* p_attnout = sym_addr(g_attnout);
    float* p_ffnh    = sym_addr(g_ffnh);
    float* p_gbar    = sym_addr(g_gbar);
    float* p_tokens  = sym_addr(g_tokens);
    float* p_qkvwg   = sym_addr(g_qkvwg);
    float* p_proj    = sym_addr(g_proj);
    float* p_pri_pad = sym_addr(g_pri_pad);
    float* p_pw_pad  = sym_addr(g_pw_pad);

    cudaFuncSetAttribute(gemm_tc, cudaFuncAttributeMaxDynamicSharedMemorySize, GTC_SMEM);
    cudaFuncSetAttribute(k_attn,  cudaFuncAttributeMaxDynamicSharedMemorySize, ATT_SMEM);

    k_zero_kl<<<1,1>>>();
    k_prep_pw<<<(KPAD*CH+255)/256,256>>>(pw);

    // 1. pre-attention LN (both streams)
    k_layernorm<<<2*CBN,256>>>(x0, x1, 0, ln_g, ln_b, 0, p_z);
    // 2. QKV (both; per-stream weights)
    gemm_tc<<<12*190,256,GTC_SMEM>>>(p_z, wqkv0, wqkv1, nullptr, nullptr, p_qkv,
        2*M1P, CH, 3*CH, 12, M1P, nullptr, 0, 0, nullptr, nullptr);
    // 3. prior similarity + mass
    k_prior_part<<<2*CB*CP*8,256>>>(pri0, pri1, conn0, conn1);
    k_conn_part<<<2*CB*8,256>>>(conn0, conn1);
    k_sw<<<2*CB,32>>>();
    // 4. prescale priors then pe GEMM (shared weights)
    k_prescale<<<(int)(((long long)2*CBPN*KPAD+255)/256),256>>>(pri0, pri1);
    gemm_tc<<<4*570,256,GTC_SMEM>>>(p_pri_pad, p_pw_pad, p_pw_pad, pb, pb, p_pe,
        2*M2P, KPAD, CH, 4, M2P, nullptr, 0, 0, nullptr, nullptr);
    // 5. fused_nh
    k_fused_nh<<<(2*X_SZ+255)/256,256>>>();
    // 6. zc = z @ f1w[512:] + f1b (shared)
    gemm_tc<<<4*190,256,GTC_SMEM>>>(p_z, f1w + CH*CH, f1w + CH*CH, f1b, f1b, p_zc,
        2*M1P, CH, CH, 4, M1P, nullptr, 0, 0, nullptr, nullptr);
    // 7. g = gelu(pe @ f1w[:512] + zc)
    gemm_tc<<<4*570,256,GTC_SMEM>>>(p_pe, f1w, f1w, nullptr, nullptr, p_h,
        2*M2P, CH, CH, 4, M2P, p_zc, 2, 1, nullptr, nullptr);
    // 8. gbar ; tokens ; qkv_wg
    k_gbar_part<<<2*CB*CP*8,256>>>();
    k_gbar_fin<<<2*CB*CP,256>>>();
    gemm_tc<<<4*2,256,GTC_SMEM>>>(p_gbar, f2w, f2w, f2b, f2b, p_tokens,
        2*MGP, CH, CH, 4, MGP, nullptr, 0, 0, nullptr, nullptr);
    gemm_tc<<<12*2,256,GTC_SMEM>>>(p_tokens, ipw, ipw, ipb, ipb, p_qkvwg,
        2*MGP, CH, 3*CH, 12, MGP, nullptr, 0, 0, nullptr, nullptr);
    // 9. tiny MHA (writes aw_, msum)
    k_wg_attn<<<2*CB,64>>>(out);
    // 10. fused attention (tensor-core; inline mask from conn+msum)
    k_attn<<<2*CB*CNH*12,256,ATT_SMEM>>>(x0, x1, conn0, conn1, alpha);
    // 11. FFN (per-stream weights); ffn2 dual-writes out + proj
    k_layernorm<<<2*CBN,256>>>(p_attnout, nullptr, 1, ln_g, ln_b, 2, p_z);
    gemm_tc<<<16*190,256,GTC_SMEM>>>(p_z, ffn_w1, ffn_w1 + (long long)CH*4*CH,
        ffn_b1, ffn_b1 + 4*CH, p_ffnh,
        2*M1P, CH, 4*CH, 16, M1P, nullptr, 0, 1, nullptr, nullptr);
    gemm_tc<<<4*190,256,GTC_SMEM>>>(p_ffnh, ffn_w2, ffn_w2 + (long long)4*CH*CH,
        ffn_b2, ffn_b2 + CH, out,
        2*M1P, 4*CH, CH, 4, M1P, p_attnout, 3, 0, p_proj, dw);

    // distillation loss (fused logsoftmax + KL)
    k_loss_all<<<CBN,256>>>();
    k_loss<<<1,1>>>(out + LOSS_OFF);
}

// round 15
// speedup vs baseline: 1.0066x; 1.0066x over previous
#include <cuda_runtime.h>
#include <math.h>

// ---------------- problem constants ----------------
#define CB   32
#define CN   379
#define CH   512
#define CNH  8
#define CP   3
#define CWGH 4
#define CHD  64          // CH/CNH
#define CBN  (CB*CN)     // 12128
#define CBPN (CB*CP*CN)  // 36384
#define CNN  (CN*CN)     // 143641
#define KPAD 384         // pri K padded to multiple of 32

// padded per-stream row regions (multiples of 128)
#define M1P  12160       // 95*128  >= CBN
#define M2P  36480       // 285*128 >= CBPN  (285 tiles/stream)
#define MGP  128         // >= CB*CP

#define X_SZ   (CBN*CH)          // 6209536
#define LOSS_OFF (2*X_SZ)
#define AWFC_OFF (LOSS_OFF+1)
#define AWSC_OFF (AWFC_OFF + CB*CP)

// gemm_tc dynamic smem: 2 stages x (128x36 + 32x136) words
#define GTC_SMEM ((2*128*36 + 2*32*136)*4)          // 71680 B
// k_attn dynamic smem: S 32x388 + Q 32x68 + Ts 32x76 + Vs 32x72
#define ATT_SMEM ((32*388 + 32*68 + 32*76 + 32*72)*4)   // 77312 B

// ---------------- static scratch (two-stream padded layouts) ----------------
static __device__ float g_z[2*M1P*CH];
static __device__ float g_qkv[(long long)2*M1P*3*CH];
static __device__ float g_pe[(long long)2*M2P*CH];
static __device__ float g_zc[2*M1P*CH];
static __device__ float g_fn[2*M1P*CH];
static __device__ float g_attnout[2*M1P*CH];
static __device__ float g_ffnh[(long long)2*M1P*4*CH];
static __device__ float g_proj[(long long)2*M1P*CH];
static __device__ float g_pri_pad[(long long)2*M2P*KPAD];
static __device__ float g_pw_pad[KPAD*CH];
static __device__ float g_hpart[570*2*512];     // per-tile segmented gelu column sums
static __device__ float g_gbar[2*MGP*CH];
static __device__ float g_tokens[2*MGP*CH];
static __device__ float g_qkvwg[2*MGP*3*CH];
static __device__ float g_dotp[2*CB*CP*8], g_psqp[2*CB*CP*8], g_pabsp[2*CB*CP*8];
static __device__ float g_csqp[2*CB*8];
static __device__ float g_sw[2*CB*CP], g_invmass[2*CB*CP], g_msum[2*CB];
static __device__ double g_kl[2];

__device__ __forceinline__ unsigned to_tf32(float v)
{
    unsigned r; asm("cvt.rna.tf32.f32 %0, %1;" : "=r"(r) : "f"(v)); return r;
}

__device__ __forceinline__ void mma8(float* c, unsigned a0, unsigned a1,
                                     unsigned a2, unsigned a3,
                                     unsigned b0, unsigned b1)
{
    asm volatile(
        "mma.sync.aligned.m16n8k8.row.col.f32.tf32.tf32.f32 "
        "{%0,%1,%2,%3}, {%4,%5,%6,%7}, {%8,%9}, {%0,%1,%2,%3};"
        : "+f"(c[0]), "+f"(c[1]), "+f"(c[2]), "+f"(c[3])
        : "r"(a0), "r"(a1), "r"(a2), "r"(a3), "r"(b0), "r"(b1));
}

// ---------------- tf32 tensor-core GEMM, dual-stream weight select -----------------
// Block tile 128x128, 256 threads = 8 warps (2m x 4n), warp tile 64x32,
// 2-stage cp.async, k-chunk 32, single barrier per chunk.
// REQUIRES K%32==0 and M multiple of 128.
// resMode: 0 none;
//          2: res[(st*M1P + b*CN + n)*Nc + gn] with gm-st*M2P=(b*CP+p)*CN+n (skip pads);
//          3: res=attnout (padded, gm*Nc); C=compact out row st*CBN+r_in (skip pads);
//             proj[gm*Nc+gn] = xn - dwp[st]*res;
//          4: gelu(acc + res[mode2 addressing]); NO C write; deterministic per-tile
//             segmented column sums -> g_hpart[by*2+seg][n0+col].
__global__ void __launch_bounds__(256,2)
gemm_tc(const float* __restrict__ A,
        const float* __restrict__ W0, const float* __restrict__ W1,
        const float* __restrict__ b0, const float* __restrict__ b1,
        float* __restrict__ C,
        int M, int K, int Nc, int gridNx, int mSplit,
        const float* __restrict__ res, int resMode, int act,
        float* __restrict__ proj, const float* __restrict__ dwp)
{
    extern __shared__ unsigned char s_raw[];
    unsigned (*As)[128][36] = (unsigned (*)[128][36])s_raw;
    unsigned (*Ws)[32][136] = (unsigned (*)[32][136])(s_raw + 2*128*36*4);

    const int t    = threadIdx.x;        // 0..255
    const int bx   = blockIdx.x % gridNx;
    const int by   = blockIdx.x / gridNx;
    const int m0   = by * 128;
    const int n0   = bx * 128;
    const int st   = (m0 >= mSplit) ? 1 : 0;
    const float* W    = st ? W1 : W0;
    const float* bias = st ? b1 : b0;

    const int lane = t & 31, warp = t >> 5;
    const int wm   = warp >> 2;          // 0..1
    const int wn   = warp & 3;           // 0..3
    const int gid  = lane >> 2;          // 0..7
    const int tid4 = lane & 3;           // 0..3

    const int ac4 = t & 7;
    const int ar0 = t >> 3;              // 0..31
    const int wc4 = t & 31;
    const int wr0 = t >> 5;              // 0..7

    const float wv = (resMode == 3) ? dwp[st] : 0.f;

    float c[4][4][4];
    #pragma unroll
    for (int i=0;i<4;i++)
        #pragma unroll
        for (int j=0;j<4;j++)
            #pragma unroll
            for (int k=0;k<4;k++) c[i][j][k]=0.f;

    auto do_chunk = [&](const unsigned (*Ab)[36], const unsigned (*Wb)[136]) {
        #pragma unroll
        for (int k8 = 0; k8 < 32; k8 += 8) {
            unsigned a[4][4], b[4][2];
            #pragma unroll
            for (int ma = 0; ma < 4; ma++) {
                int rb = wm*64 + ma*16;
                a[ma][0] = Ab[rb + gid    ][k8 + tid4    ];
                a[ma][1] = Ab[rb + gid + 8][k8 + tid4    ];
                a[ma][2] = Ab[rb + gid    ][k8 + tid4 + 4];
                a[ma][3] = Ab[rb + gid + 8][k8 + tid4 + 4];
            }
            #pragma unroll
            for (int nb = 0; nb < 4; nb++) {
                int cn = wn*32 + nb*8 + gid;
                b[nb][0] = Wb[k8 + tid4    ][cn];
                b[nb][1] = Wb[k8 + tid4 + 4][cn];
            }
            #pragma unroll
            for (int ma = 0; ma < 4; ma++)
                #pragma unroll
                for (int nb = 0; nb < 4; nb++)
                    mma8(c[ma][nb], a[ma][0], a[ma][1], a[ma][2], a[ma][3],
                         b[nb][0], b[nb][1]);
        }
    };

    auto issue = [&](int kk, int buf) {
        #pragma unroll
        for (int v = 0; v < 4; v++) {            // A: 128x32
            int row = ar0 + 32*v;
            int gm  = m0 + row;
            const float* src = A + (long long)gm*K + kk + ac4*4;
            unsigned dst = (unsigned)__cvta_generic_to_shared(&As[buf][row][ac4*4]);
            asm volatile("cp.async.ca.shared.global [%0], [%1], 16, 16;"
                         :: "r"(dst), "l"(src));
        }
        #pragma unroll
        for (int v = 0; v < 4; v++) {            // W: 32x128
            int row = wr0 + 8*v;
            int gk  = kk + row;
            const float* src = W + (long long)gk*Nc + n0 + wc4*4;
            unsigned dst = (unsigned)__cvta_generic_to_shared(&Ws[buf][row][wc4*4]);
            asm volatile("cp.async.ca.shared.global [%0], [%1], 16, 16;"
                         :: "r"(dst), "l"(src));
        }
        asm volatile("cp.async.commit_group;");
    };

    int nb = K >> 5;
    issue(0, 0);
    int cur = 0;
    for (int cidx = 0; cidx < nb; cidx++) {
        asm volatile("cp.async.wait_group 0;" ::: "memory");
        __syncthreads();
        if (cidx + 1 < nb) issue((cidx+1) << 5, cur ^ 1);
        do_chunk(As[cur], Ws[cur]);
        cur ^= 1;
    }

    if (resMode == 4) {
        // gelu + segmented column sums, no C write. Reuse smem for partials.
        __syncthreads();
        float (*part)[16][132] = (float (*)[16][132])s_raw;
        const int g0 = (m0 - st*M2P) / CN;     // tile first-row group
        const int slot = wm*8 + gid;
        #pragma unroll
        for (int nb2 = 0; nb2 < 4; nb2++) {
            #pragma unroll
            for (int cc = 0; cc < 2; cc++) {
                int lcol = wn*32 + nb2*8 + 2*tid4 + cc;
                int gn = n0 + lcol;
                float s0 = 0.f, s1 = 0.f;
                #pragma unroll
                for (int ma = 0; ma < 4; ma++) {
                    #pragma unroll
                    for (int rr = 0; rr < 2; rr++) {
                        int gm = m0 + wm*64 + ma*16 + gid + rr*8;
                        int g2 = gm - st*M2P;
                        if (g2 >= CBPN) continue;
                        int grp = g2 / CN;
                        int nn  = g2 - grp*CN;
                        float v = c[ma][nb2][rr*2 + cc]
                                + res[((long long)(st*M1P + (grp/CP)*CN + nn))*Nc + gn];
                        v = 0.5f * v * (1.f + erff(v * 0.70710678118654752f));
                        if (grp == g0) s0 += v; else s1 += v;
                    }
                }
                part[0][slot][lcol] = s0;
                part[1][slot][lcol] = s1;
            }
        }
        __syncthreads();
        int lcol = t & 127, sg = t >> 7;
        float sum = 0.f;
        #pragma unroll
        for (int sl = 0; sl < 16; sl++) sum += part[sg][sl][lcol];
        g_hpart[((long long)by*2 + sg)*512 + n0 + lcol] = sum;
        return;
    }

    // ---- generic epilogue ----
    #pragma unroll
    for (int ma = 0; ma < 4; ma++) {
        #pragma unroll
        for (int rr = 0; rr < 2; rr++) {
            int gm = m0 + wm*64 + ma*16 + gid + rr*8;
            long long resBase = -1;
            int outRow = -1;
            if (resMode == 2) {
                int g2 = gm - st*M2P;
                if (g2 < CBPN) {
                    int bb = g2 / (CP * CN);
                    int nn = g2 % CN;
                    resBase = ((long long)(st*M1P + bb*CN + nn)) * Nc;
                }
            } else if (resMode == 3) {
                resBase = (long long)gm * Nc;
                int r_in = gm - st*mSplit;
                if (r_in < CBN) outRow = st*CBN + r_in;
            }
            if (resMode == 2 && resBase < 0) continue;  // pad row: skip
            #pragma unroll
            for (int nb2 = 0; nb2 < 4; nb2++) {
                #pragma unroll
                for (int cc = 0; cc < 2; cc++) {
                    int gn = n0 + wn*32 + nb2*8 + 2*tid4 + cc;
                    float v = c[ma][nb2][rr*2 + cc];
                    if (bias) v += bias[gn];
                    if (resMode == 3) {
                        float r = res[resBase + gn];
                        float xn = v + r;
                        if (outRow >= 0) C[(long long)outRow * Nc + gn] = xn;
                        proj[(long long)gm * Nc + gn] = xn - wv*r;
                        continue;
                    }
                    if (resMode == 2) v += res[resBase + gn];
                    if (act) v = 0.5f * v * (1.f + erff(v * 0.70710678118654752f));
                    C[(long long)gm * Nc + gn] = v;
                }
            }
        }
    }
}

// ---------------- prescale priors (both streams) ----------------
__global__ void k_prescale(const float* __restrict__ pri0, const float* __restrict__ pri1)
{
    long long idx = (long long)blockIdx.x*blockDim.x + threadIdx.x;
    if (idx >= (long long)2*CBPN*KPAD) return;
    int s = (int)(idx / ((long long)CBPN*KPAD));
    long long rem = idx - (long long)s*CBPN*KPAD;
    int k = (int)(rem % KPAD);
    long long rowc = rem / KPAD;
    const float* pri = s ? pri1 : pri0;
    float v = 0.f;
    if (k < CN) v = pri[rowc*CN + k] * g_invmass[s*CB*CP + (int)(rowc / CN)];
    g_pri_pad[((long long)s*M2P + rowc)*KPAD + k] = __uint_as_float(to_tf32(v));
}

__global__ void k_prep_pw(const float* __restrict__ pw)
{
    int idx = blockIdx.x*blockDim.x + threadIdx.x;
    if (idx >= KPAD*CH) return;
    int r = idx / CH, c = idx % CH;
    float v = (r < CN) ? pw[r*CH + c] : 0.f;
    g_pw_pad[idx] = __uint_as_float(to_tf32(v));
}

// ---------------- fused attention (tensor-core QK^T and PV; inline mask) -----------
__global__ void __launch_bounds__(256) k_attn(const float* __restrict__ x0,
                                              const float* __restrict__ x1,
                                              const float* __restrict__ conn0,
                                              const float* __restrict__ conn1,
                                              const float* __restrict__ alpha)
{
    extern __shared__ unsigned char s_raw[];
    float (*S)[388]  = (float (*)[388])s_raw;
    float (*Qs)[68]  = (float (*)[68])(s_raw + 32*388*4);
    float (*Ts)[76]  = (float (*)[76])(s_raw + (32*388 + 32*68)*4);
    float (*Vs)[72]  = (float (*)[72])(s_raw + (32*388 + 32*68 + 32*76)*4);

    int blk = blockIdx.x;            // 2*CB*CNH*12
    int s = blk / (CB*96);
    int rem = blk % (CB*96);
    int b = rem / 96;
    int r2 = rem % 96;
    int h = r2 / 12;
    int i0 = (r2 % 12) * 32;
    int t = threadIdx.x;
    const float* x    = s ? x1 : x0;
    const float* conn = s ? conn1 : conn0;
    const long long qbase = (long long)s*M1P + (long long)b*CN;

    const int lane = t & 31, warp = t >> 5;
    const int wm   = warp >> 2;      // 0..1
    const int wn   = warp & 3;       // 0..3
    const int gid  = lane >> 2;      // 0..7
    const int tid4 = lane & 3;       // 0..3
    const int ldr  = t >> 3;         // 0..31
    const int ldc  = (t & 7) * 8;

    // load Q tile 32x64
    {
        int gi = i0 + ldr;
        const float* src = g_qkv + (qbase + (gi < CN ? gi : 0))*3*CH + h*CHD + ldc;
        #pragma unroll
        for (int u = 0; u < 8; u++) Qs[ldr][ldc+u] = (gi < CN) ? src[u] : 0.f;
    }
    __syncthreads();

    // ---- phase 1: S = Q K^T ----
    for (int j0 = 0; j0 < KPAD; j0 += 32) {
        {
            int gj = j0 + ldr;
            const float* src = g_qkv + (qbase + (gj < CN ? gj : 0))*3*CH + CH + h*CHD + ldc;
            #pragma unroll
            for (int u = 0; u < 8; u++) Ts[ldr][ldc+u] = (gj < CN) ? src[u] : 0.f;
        }
        __syncthreads();
        float c4[4] = {0.f,0.f,0.f,0.f};
        #pragma unroll
        for (int k8 = 0; k8 < 64; k8 += 8) {
            unsigned a0 = __float_as_uint(Qs[wm*16+gid  ][k8+tid4  ]);
            unsigned a1 = __float_as_uint(Qs[wm*16+gid+8][k8+tid4  ]);
            unsigned a2 = __float_as_uint(Qs[wm*16+gid  ][k8+tid4+4]);
            unsigned a3 = __float_as_uint(Qs[wm*16+gid+8][k8+tid4+4]);
            unsigned b0 = __float_as_uint(Ts[wn*8+gid][k8+tid4  ]);
            unsigned b1 = __float_as_uint(Ts[wn*8+gid][k8+tid4+4]);
            mma8(c4, a0, a1, a2, a3, b0, b1);
        }
        int col = j0 + wn*8 + 2*tid4;
        S[wm*16+gid  ][col  ] = c4[0];
        S[wm*16+gid  ][col+1] = c4[1];
        S[wm*16+gid+8][col  ] = c4[2];
        S[wm*16+gid+8][col+1] = c4[3];
        __syncthreads();
    }

    // ---- phase 2: inline mask + scale + row softmax ----
    {
        float a2c  = alpha[0]*0.5f;
        float base = a2c * g_msum[s*CB + b];
        float om   = 1.f - a2c;
        for (int rr = 0; rr < 4; rr++) {
            int i = warp*4 + rr;
            int gi = i0 + i;
            if (gi >= CN) continue;
            const float* crow = conn + (long long)gi*CN + (long long)b*CNN;
            float mx = -1e30f;
            for (int jc = lane; jc < CN; jc += 32) {
                float m = tanhf(base + om*crow[jc]);
                float v = 0.125f * S[i][jc] * (1.f + m);
                S[i][jc] = v;
                mx = fmaxf(mx, v);
            }
            #pragma unroll
            for (int o = 16; o > 0; o >>= 1) mx = fmaxf(mx, __shfl_xor_sync(~0u, mx, o));
            float sum = 0.f;
            for (int jc = lane; jc < CN; jc += 32) {
                float e = expf(S[i][jc] - mx);
                S[i][jc] = e;
                sum += e;
            }
            #pragma unroll
            for (int o = 16; o > 0; o >>= 1) sum += __shfl_xor_sync(~0u, sum, o);
            float inv = 1.f / sum;
            for (int jc = lane; jc < CN; jc += 32) S[i][jc] *= inv;
            for (int jc = CN + lane; jc < KPAD; jc += 32) S[i][jc] = 0.f;
        }
    }

    // ---- phase 3: ctx = P @ V ----
    float acc[2][4] = {};
    for (int j0 = 0; j0 < KPAD; j0 += 32) {
        __syncthreads();
        {
            int gj = j0 + ldr;
            const float* src = g_qkv + (qbase + (gj < CN ? gj : 0))*3*CH + 2*CH + h*CHD + ldc;
            #pragma unroll
            for (int u = 0; u < 8; u++) Vs[ldr][ldc+u] = (gj < CN) ? src[u] : 0.f;
        }
        __syncthreads();
        #pragma unroll
        for (int k8 = 0; k8 < 32; k8 += 8) {
            unsigned a0 = __float_as_uint(S[wm*16+gid  ][j0+k8+tid4  ]);
            unsigned a1 = __float_as_uint(S[wm*16+gid+8][j0+k8+tid4  ]);
            unsigned a2 = __float_as_uint(S[wm*16+gid  ][j0+k8+tid4+4]);
            unsigned a3 = __float_as_uint(S[wm*16+gid+8][j0+k8+tid4+4]);
            #pragma unroll
            for (int nt = 0; nt < 2; nt++) {
                int cn = wn*16 + nt*8 + gid;
                unsigned b0 = __float_as_uint(Vs[k8+tid4  ][cn]);
                unsigned b1 = __float_as_uint(Vs[k8+tid4+4][cn]);
                mma8(acc[nt], a0, a1, a2, a3, b0, b1);
            }
        }
    }
    // write: attnout = x + ctx + fn
    #pragma unroll
    for (int nt = 0; nt < 2; nt++) {
        #pragma unroll
        for (int rr = 0; rr < 2; rr++) {
            int gi = i0 + wm*16 + gid + rr*8;
            if (gi >= CN) continue;
            #pragma unroll
            for (int cc = 0; cc < 2; cc++) {
                int d = h*CHD + wn*16 + nt*8 + 2*tid4 + cc;
                long long oc = ((long long)(b*CN + gi))*CH + d;   // compact (x)
                long long op = (qbase + gi)*CH + d;                // padded
                g_attnout[op] = x[oc] + g_fn[op] + acc[nt][rr*2 + cc];
            }
        }
    }
}

// ---------------- layernorm (both streams; optional padded input) ----------------
__global__ void k_layernorm(const float* __restrict__ x0, const float* __restrict__ x1,
                            int inPadded, const float* __restrict__ g,
                            const float* __restrict__ b, int gRow0, float* __restrict__ z)
{
    int row = blockIdx.x;                 // 0..2*CBN-1
    int s = row >= CBN;
    int rin = row - s*CBN;
    const float* xr;
    if (inPadded) xr = x0 + ((long long)s*M1P + rin)*CH;
    else          xr = (s ? x1 : x0) + (long long)rin*CH;
    float* zr = z + ((long long)s*M1P + rin)*CH;
    const float* gp = g + (gRow0 + s)*CH;
    const float* bp = b + (gRow0 + s)*CH;
    __shared__ float red[256];
    int t = threadIdx.x;
    float v0 = xr[t], v1 = xr[t+256];
    red[t] = v0+v1; __syncthreads();
    for (int o=128;o>0;o>>=1){ if(t<o) red[t]+=red[t+o]; __syncthreads(); }
    float mean = red[0]*(1.f/CH); __syncthreads();
    float d0=v0-mean, d1=v1-mean;
    red[t]=d0*d0+d1*d1; __syncthreads();
    for (int o=128;o>0;o>>=1){ if(t<o) red[t]+=red[t+o]; __syncthreads(); }
    float rstd = rsqrtf(red[0]*(1.f/CH) + 1e-5f);
    zr[t]     = d0*rstd*gp[t]     + bp[t];
    zr[t+256] = d1*rstd*gp[t+256] + bp[t+256];
}

// ---------------- merged prior + conn reductions (conn read once) ----------------
__global__ void k_prior_all(const float* __restrict__ pri0, const float* __restrict__ pri1,
                            const float* __restrict__ conn0, const float* __restrict__ conn1)
{
    int blk = blockIdx.x;           // 2*CB*8
    int s = blk / (CB*8);
    int rem = blk % (CB*8);
    int b = rem >> 3, ch = rem & 7;
    const float* pri  = (s ? pri1 : pri0) + (long long)(b*CP)*CNN;
    const float* conn = (s ? conn1 : conn0) + (long long)b*CNN;
    const int CHK = (CNN + 7) / 8;
    int lo = ch*CHK, hi = lo + CHK; if (hi > CNN) hi = CNN;
    float acc[10] = {};   // dot0,q0,ab0, dot1,q1,ab1, dot2,q2,ab2, csq
    for (int i = lo + threadIdx.x; i < hi; i += blockDim.x) {
        float cv = conn[i];
        acc[9] += cv*cv;
        #pragma unroll
        for (int p = 0; p < CP; p++) {
            float pv = pri[(long long)p*CNN + i];
            acc[p*3+0] += pv*cv;
            acc[p*3+1] += pv*pv;
            acc[p*3+2] += fabsf(pv);
        }
    }
    __shared__ float red[10][256];
    int t = threadIdx.x;
    #pragma unroll
    for (int k = 0; k < 10; k++) red[k][t] = acc[k];
    __syncthreads();
    for (int o = 128; o > 0; o >>= 1) {
        if (t < o)
            #pragma unroll
            for (int k = 0; k < 10; k++) red[k][t] += red[k][t+o];
        __syncthreads();
    }
    if (t == 0) {
        #pragma unroll
        for (int p = 0; p < CP; p++) {
            int bp = (s*CB + b)*CP + p;
            g_dotp[bp*8+ch]  = red[p*3+0][0];
            g_psqp[bp*8+ch]  = red[p*3+1][0];
            g_pabsp[bp*8+ch] = red[p*3+2][0];
        }
        g_csqp[(s*CB+b)*8+ch] = red[9][0];
    }
}

__global__ void k_sw()
{
    if (threadIdx.x) return;
    int gb = blockIdx.x;            // 0..2*CB-1
    float csq=0;
    #pragma unroll
    for (int u=0;u<8;u++) csq += g_csqp[gb*8+u];
    float cn = fmaxf(sqrtf(csq), 1e-12f);
    float s[CP], mx=-1e30f;
    for (int p=0;p<CP;p++){
        int bp = gb*CP+p;
        float dot=0, sq=0, ab=0;
        #pragma unroll
        for (int u=0;u<8;u++){ dot+=g_dotp[bp*8+u]; sq+=g_psqp[bp*8+u]; ab+=g_pabsp[bp*8+u]; }
        float pn = fmaxf(sqrtf(sq), 1e-12f);
        s[p] = dot/(cn*pn);
        mx = fmaxf(mx, s[p]);
        g_invmass[bp] = 1.f/ab;
    }
    float sum=0;
    for (int p=0;p<CP;p++){ s[p]=expf(s[p]-mx); sum+=s[p]; }
    for (int p=0;p<CP;p++) g_sw[gb*CP+p]=s[p]/sum;
}

// ---------------- fused_nh (both streams) ----------------
__global__ void k_fused_nh()
{
    long long idx = (long long)blockIdx.x*blockDim.x + threadIdx.x;
    if (idx >= (long long)2*CBN*CH) return;
    int s = (int)(idx / X_SZ);
    long long rem = idx - (long long)s*X_SZ;
    int c = (int)(rem % CH);
    long long bn = rem / CH;
    int b = (int)(bn / CN), n = (int)(bn % CN);
    float acc=0;
    #pragma unroll
    for (int p=0;p<CP;p++)
        acc += g_sw[(s*CB+b)*CP+p] *
               g_pe[((long long)s*M2P + (long long)(b*CP+p)*CN + n)*CH + c];
    g_fn[((long long)s*M1P + bn)*CH + c] = acc;
}

// ---------------- gbar from per-tile segmented partials ----------------
__global__ void k_gbar_fin2()
{
    int gbp = blockIdx.x;           // 2*CB*CP
    int s = gbp / (CB*CP);
    int bp = gbp % (CB*CP);
    int c = threadIdx.x;            // 256
    int r0 = bp*CN, r1 = r0 + CN;
    int t0 = r0 >> 7, t1 = (r1-1) >> 7;
    float a0=0, a1=0;
    for (int byl = t0; byl <= t1; byl++){
        int g0t = (byl << 7) / CN;
        int seg = bp - g0t;         // 0 or 1
        const float* r = g_hpart + ((long long)((s*285 + byl)*2 + seg))*512;
        a0 += r[c]; a1 += r[c+256];
    }
    g_gbar[(s*MGP+bp)*CH+c]     = a0*(1.f/CN);
    g_gbar[(s*MGP+bp)*CH+c+256] = a1*(1.f/CN);
}

// ---------------- tiny weight-gen MHA (both streams) ----------------
__global__ void k_wg_attn(float* __restrict__ out)
{
    int gb = blockIdx.x;            // 0..2*CB-1
    int s = gb / CB;
    int b = gb % CB;
    __shared__ float logit[CWGH*CP*CP];
    int t = threadIdx.x;            // 64 threads
    if (t < CWGH*CP*CP) {
        int h = t/(CP*CP); int i = (t/CP)%CP; int j = t%CP;
        const float* q = g_qkvwg + (long long)(s*MGP + b*CP+i)*3*CH + h*128;
        const float* k = g_qkvwg + (long long)(s*MGP + b*CP+j)*3*CH + CH + h*128;
        float d=0;
        for (int x=0;x<128;x++) d += q[x]*k[x];
        logit[t] = d*0.08838834764831845f;   // 1/sqrt(128)
    }
    __syncthreads();
    if (t==0) {
        float aw[CP]={0,0,0};
        for (int h=0;h<CWGH;h++) for (int i=0;i<CP;i++) {
            float mx=-1e30f;
            for (int j=0;j<CP;j++) mx=fmaxf(mx, logit[(h*CP+i)*CP+j]);
            float e[CP], ss=0;
            for (int j=0;j<CP;j++){ e[j]=expf(logit[(h*CP+i)*CP+j]-mx); ss+=e[j]; }
            for (int j=0;j<CP;j++) aw[j]+= e[j]/ss;
        }
        for (int j=0;j<CP;j++) aw[j] *= (1.f/(CWGH*CP));
        float mx=-1e30f;
        for (int j=0;j<CP;j++) mx=fmaxf(mx, aw[j]);
        float ss=0, e[CP];
        for (int j=0;j<CP;j++){ e[j]=expf((aw[j]-mx)*100.f); ss+=e[j]; }  // temp 0.01
        float msum=0;
        float* awp = out + (s ? AWSC_OFF : AWFC_OFF) + b*CP;
        for (int j=0;j<CP;j++){ float a=e[j]/ss; awp[j]=a; msum+=a; }
        g_msum[gb]=msum;
    }
}

// ---------------- fused logsoftmax + KL (per row-pair) ----------------
__global__ void k_loss_all()
{
    int r = blockIdx.x;             // 0..CBN-1
    const float* p0 = g_proj + (long long)r*CH;
    const float* p1 = g_proj + ((long long)M1P + r)*CH;
    __shared__ float red[256];
    __shared__ double d1[256], d2[256];
    int t = threadIdx.x;
    float a0 = p0[t], b0 = p0[t+256];
    float a1 = p1[t], b1 = p1[t+256];

    red[t] = fmaxf(a0,b0); __syncthreads();
    for (int o=128;o>0;o>>=1){ if(t<o) red[t]=fmaxf(red[t],red[t+o]); __syncthreads(); }
    float mx0 = red[0]; __syncthreads();
    red[t] = expf(a0-mx0)+expf(b0-mx0); __syncthreads();
    for (int o=128;o>0;o>>=1){ if(t<o) red[t]+=red[t+o]; __syncthreads(); }
    float lse0 = logf(red[0]) + mx0; __syncthreads();
    red[t] = fmaxf(a1,b1); __syncthreads();
    for (int o=128;o>0;o>>=1){ if(t<o) red[t]=fmaxf(red[t],red[t+o]); __syncthreads(); }
    float mx1 = red[0]; __syncthreads();
    red[t] = expf(a1-mx1)+expf(b1-mx1); __syncthreads();
    for (int o=128;o>0;o>>=1){ if(t<o) red[t]+=red[t+o]; __syncthreads(); }
    float lse1 = logf(red[0]) + mx1; __syncthreads();

    float lf0 = a0 - lse0, lf1 = b0 - lse0;
    float ls0 = a1 - lse1, ls1 = b1 - lse1;
    d1[t] = (double)(expf(ls0)*(ls0-lf0)) + (double)(expf(ls1)*(ls1-lf1));
    d2[t] = (double)(expf(lf0)*(lf0-ls0)) + (double)(expf(lf1)*(lf1-ls1));
    __syncthreads();
    for (int o=128;o>0;o>>=1){ if(t<o){ d1[t]+=d1[t+o]; d2[t]+=d2[t+o]; } __syncthreads(); }
    if (t==0){ atomicAdd(&g_kl[0], d1[0]); atomicAdd(&g_kl[1], d2[0]); }
}

__global__ void k_zero_kl(){ g_kl[0]=0.0; g_kl[1]=0.0; }

__global__ void k_loss(float* __restrict__ out)
{
    out[0] = (float)(0.5*(g_kl[0]+g_kl[1])/(double)CBN);
}

// ---------------- host orchestration ----------------
// CRITICAL: __device__ symbols passed as kernel ARGUMENTS must be resolved via
// cudaGetSymbolAddress (host shadow address + GB300 ATS silently reads host RAM).
static float* sym_addr(const void* symbol)
{
    void* p = nullptr;
    cudaGetSymbolAddress(&p, symbol);
    return (float*)p;
}

extern "C" void kernel_launch(void* const* d_in, const int* in_sizes, int n_in,
                              void* d_out, int out_size)
{
    const float* x0      = (const float*)d_in[0];
    const float* x1      = (const float*)d_in[1];
    const float* pri0    = (const float*)d_in[2];
    const float* pri1    = (const float*)d_in[3];
    const float* conn0   = (const float*)d_in[4];
    const float* conn1   = (const float*)d_in[5];
    const float* dw      = (const float*)d_in[6];
    const float* wqkv0   = (const float*)d_in[7];
    const float* wqkv1   = (const float*)d_in[8];
    const float* ln_g    = (const float*)d_in[9];
    const float* ln_b    = (const float*)d_in[10];
    const float* ffn_w1  = (const float*)d_in[11];
    const float* ffn_b1  = (const float*)d_in[12];
    const float* ffn_w2  = (const float*)d_in[13];
    const float* ffn_b2  = (const float*)d_in[14];
    const float* pw      = (const float*)d_in[15];
    const float* pb      = (const float*)d_in[16];
    const float* f1w     = (const float*)d_in[17];
    const float* f1b     = (const float*)d_in[18];
    const float* f2w     = (const float*)d_in[19];
    const float* f2b     = (const float*)d_in[20];
    const float* ipw     = (const float*)d_in[21];
    const float* ipb     = (const float*)d_in[22];
    const float* alpha   = (const float*)d_in[23];
    float* out = (float*)d_out;

    float* p_z       = sym_addr(g_z);
    float* p_qkv     = sym_addr(g_qkv);
    float* p_pe      = sym_addr(g_pe);
    float* p_zc      = sym_addr(g_zc);
    float* p_attnout = sym_addr(g_attnout);
    float* p_ffnh    = sym_addr(g_ffnh);
    float* p_gbar    = sym_addr(g_gbar);
    float* p_tokens  = sym_addr(g_tokens);
    float* p_qkvwg   = sym_addr(g_qkvwg);
    float* p_proj    = sym_addr(g_proj);
    float* p_pri_pad = sym_addr(g_pri_pad);
    float* p_pw_pad  = sym_addr(g_pw_pad);

    cudaFuncSetAttribute(gemm_tc, cudaFuncAttributeMaxDynamicSharedMemorySize, GTC_SMEM);
    cudaFuncSetAttribute(k_attn,  cudaFuncAttributeMaxDynamicSharedMemorySize, ATT_SMEM);

    k_zero_kl<<<1,1>>>();
    k_prep_pw<<<(KPAD*CH+255)/256,256>>>(pw);

    // 1. pre-attention LN (both streams)
    k_layernorm<<<2*CBN,256>>>(x0, x1, 0, ln_g, ln_b, 0, p_z);
    // 2. QKV (both; per-stream weights)
    gemm_tc<<<12*190,256,GTC_SMEM>>>(p_z, wqkv0, wqkv1, nullptr, nullptr, p_qkv,
        2*M1P, CH, 3*CH, 12, M1P, nullptr, 0, 0, nullptr, nullptr);
    // 3. prior similarity + mass (merged conn/pri reductions)
    k_prior_all<<<2*CB*8,256>>>(pri0, pri1, conn0, conn1);
    k_sw<<<2*CB,32>>>();
    // 4. prescale priors then pe GEMM (shared weights)
    k_prescale<<<(int)(((long long)2*CBPN*KPAD+255)/256),256>>>(pri0, pri1);
    gemm_tc<<<4*570,256,GTC_SMEM>>>(p_pri_pad, p_pw_pad, p_pw_pad, pb, pb, p_pe,
        2*M2P, KPAD, CH, 4, M2P, nullptr, 0, 0, nullptr, nullptr);
    // 5. fused_nh
    k_fused_nh<<<(2*X_SZ+255)/256,256>>>();
    // 6. zc = z @ f1w[512:] + f1b (shared)
    gemm_tc<<<4*190,256,GTC_SMEM>>>(p_z, f1w + CH*CH, f1w + CH*CH, f1b, f1b, p_zc,
        2*M1P, CH, CH, 4, M1P, nullptr, 0, 0, nullptr, nullptr);
    // 7. gelu(pe @ f1w[:512] + zc) -> segmented column sums only (resMode 4, no g_h)
    gemm_tc<<<4*570,256,GTC_SMEM>>>(p_pe, f1w, f1w, nullptr, nullptr, nullptr,
        2*M2P, CH, CH, 4, M2P, p_zc, 4, 1, nullptr, nullptr);
    // 8. gbar from partials ; tokens ; qkv_wg
    k_gbar_fin2<<<2*CB*CP,256>>>();
    gemm_tc<<<4*2,256,GTC_SMEM>>>(p_gbar, f2w, f2w, f2b, f2b, p_tokens,
        2*MGP, CH, CH, 4, MGP, nullptr, 0, 0, nullptr, nullptr);
    gemm_tc<<<12*2,256,GTC_SMEM>>>(p_tokens, ipw, ipw, ipb, ipb, p_qkvwg,
        2*MGP, CH, 3*CH, 12, MGP, nullptr, 0, 0, nullptr, nullptr);
    // 9. tiny MHA (writes aw_, msum)
    k_wg_attn<<<2*CB,64>>>(out);
    // 10. fused attention (tensor-core; inline mask from conn+msum)
    k_attn<<<2*CB*CNH*12,256,ATT_SMEM>>>(x0, x1, conn0, conn1, alpha);
    // 11. FFN (per-stream weights); ffn2 dual-writes out + proj
    k_layernorm<<<2*CBN,256>>>(p_attnout, nullptr, 1, ln_g, ln_b, 2, p_z);
    gemm_tc<<<16*190,256,GTC_SMEM>>>(p_z, ffn_w1, ffn_w1 + (long long)CH*4*CH,
        ffn_b1, ffn_b1 + 4*CH, p_ffnh,
        2*M1P, CH, 4*CH, 16, M1P, nullptr, 0, 1, nullptr, nullptr);
    gemm_tc<<<4*190,256,GTC_SMEM>>>(p_ffnh, ffn_w2, ffn_w2 + (long long)4*CH*CH,
        ffn_b2, ffn_b2 + CH, out,
        2*M1P, 4*CH, CH, 4, M1P, p_attnout, 3, 0, p_proj, dw);

    // distillation loss (fused logsoftmax + KL)
    k_loss_all<<<CBN,256>>>();
    k_loss<<<1,1>>>(out + LOSS_OFF);
}

// round 16
// speedup vs baseline: 1.0671x; 1.0601x over previous
#include <cuda_runtime.h>
#include <math.h>

// ---------------- problem constants ----------------
#define CB   32
#define CN   379
#define CH   512
#define CNH  8
#define CP   3
#define CWGH 4
#define CHD  64          // CH/CNH
#define CBN  (CB*CN)     // 12128
#define CBPN (CB*CP*CN)  // 36384
#define CNN  (CN*CN)     // 143641
#define KPAD 384         // pri K padded to multiple of 32

// padded per-stream row regions (multiples of 128)
#define M1P  12160       // 95*128  >= CBN
#define M2P  36480       // 285*128 >= CBPN  (285 tiles/stream)
#define MGP  128         // >= CB*CP

#define X_SZ   (CBN*CH)          // 6209536
#define LOSS_OFF (2*X_SZ)
#define AWFC_OFF (LOSS_OFF+1)
#define AWSC_OFF (AWFC_OFF + CB*CP)

// gemm_tc dynamic smem: 2 stages x (128x36 + 32x136) words
#define GTC_SMEM ((2*128*36 + 2*32*136)*4)          // 71680 B
// k_attn dynamic smem: S 64x388 + Q 64x68 + Ts 32x76 + Vs 32x72
#define ATT_SMEM ((64*388 + 64*68 + 32*76 + 32*72)*4)   // 135680 B

// ---------------- static scratch (two-stream padded layouts) ----------------
static __device__ float g_z[2*M1P*CH];
static __device__ float g_qkv[(long long)2*M1P*3*CH];
static __device__ float g_pe[(long long)2*M2P*CH];
static __device__ float g_zc[2*M1P*CH];
static __device__ float g_fn[2*M1P*CH];
static __device__ float g_attnout[2*M1P*CH];
static __device__ float g_ffnh[(long long)2*M1P*4*CH];
static __device__ float g_proj[(long long)2*M1P*CH];
static __device__ float g_pri_pad[(long long)2*M2P*KPAD];
static __device__ float g_pw_pad[KPAD*CH];
static __device__ float g_hpart[570*2*512];     // per-tile segmented gelu column sums
static __device__ float g_gbar[2*MGP*CH];
static __device__ float g_tokens[2*MGP*CH];
static __device__ float g_qkvwg[2*MGP*3*CH];
static __device__ float g_dotp[2*CB*CP*8], g_psqp[2*CB*CP*8], g_pabsp[2*CB*CP*8];
static __device__ float g_csqp[2*CB*8];
static __device__ float g_sw[2*CB*CP], g_invmass[2*CB*CP], g_msum[2*CB];
static __device__ double g_kl[2];

__device__ __forceinline__ unsigned to_tf32(float v)
{
    unsigned r; asm("cvt.rna.tf32.f32 %0, %1;" : "=r"(r) : "f"(v)); return r;
}

__device__ __forceinline__ void mma8(float* c, unsigned a0, unsigned a1,
                                     unsigned a2, unsigned a3,
                                     unsigned b0, unsigned b1)
{
    asm volatile(
        "mma.sync.aligned.m16n8k8.row.col.f32.tf32.tf32.f32 "
        "{%0,%1,%2,%3}, {%4,%5,%6,%7}, {%8,%9}, {%0,%1,%2,%3};"
        : "+f"(c[0]), "+f"(c[1]), "+f"(c[2]), "+f"(c[3])
        : "r"(a0), "r"(a1), "r"(a2), "r"(a3), "r"(b0), "r"(b1));
}

// ---------------- tf32 tensor-core GEMM, dual-stream weight select -----------------
// Block tile 128x128, 256 threads = 8 warps (2m x 4n), warp tile 64x32,
// 2-stage cp.async, k-chunk 32, single barrier per chunk.
// REQUIRES K%32==0 and M multiple of 128.
// resMode: 0 none;
//          2: res[(st*M1P + b*CN + n)*Nc + gn] with gm-st*M2P=(b*CP+p)*CN+n (skip pads);
//          3: res=attnout (padded, gm*Nc); C=compact out row st*CBN+r_in (skip pads);
//             proj[gm*Nc+gn] = xn - dwp[st]*res;
//          4: gelu(acc + res[mode2 addressing]); NO C write; deterministic per-tile
//             segmented column sums -> g_hpart[by*2+seg][n0+col].
__global__ void __launch_bounds__(256,2)
gemm_tc(const float* __restrict__ A,
        const float* __restrict__ W0, const float* __restrict__ W1,
        const float* __restrict__ b0, const float* __restrict__ b1,
        float* __restrict__ C,
        int M, int K, int Nc, int gridNx, int mSplit,
        const float* __restrict__ res, int resMode, int act,
        float* __restrict__ proj, const float* __restrict__ dwp)
{
    extern __shared__ unsigned char s_raw[];
    unsigned (*As)[128][36] = (unsigned (*)[128][36])s_raw;
    unsigned (*Ws)[32][136] = (unsigned (*)[32][136])(s_raw + 2*128*36*4);

    const int t    = threadIdx.x;        // 0..255
    const int bx   = blockIdx.x % gridNx;
    const int by   = blockIdx.x / gridNx;
    const int m0   = by * 128;
    const int n0   = bx * 128;
    const int st   = (m0 >= mSplit) ? 1 : 0;
    const float* W    = st ? W1 : W0;
    const float* bias = st ? b1 : b0;

    const int lane = t & 31, warp = t >> 5;
    const int wm   = warp >> 2;          // 0..1
    const int wn   = warp & 3;           // 0..3
    const int gid  = lane >> 2;          // 0..7
    const int tid4 = lane & 3;           // 0..3

    const int ac4 = t & 7;
    const int ar0 = t >> 3;              // 0..31
    const int wc4 = t & 31;
    const int wr0 = t >> 5;              // 0..7

    const float wv = (resMode == 3) ? dwp[st] : 0.f;

    float c[4][4][4];
    #pragma unroll
    for (int i=0;i<4;i++)
        #pragma unroll
        for (int j=0;j<4;j++)
            #pragma unroll
            for (int k=0;k<4;k++) c[i][j][k]=0.f;

    auto do_chunk = [&](const unsigned (*Ab)[36], const unsigned (*Wb)[136]) {
        #pragma unroll
        for (int k8 = 0; k8 < 32; k8 += 8) {
            unsigned a[4][4], b[4][2];
            #pragma unroll
            for (int ma = 0; ma < 4; ma++) {
                int rb = wm*64 + ma*16;
                a[ma][0] = Ab[rb + gid    ][k8 + tid4    ];
                a[ma][1] = Ab[rb + gid + 8][k8 + tid4    ];
                a[ma][2] = Ab[rb + gid    ][k8 + tid4 + 4];
                a[ma][3] = Ab[rb + gid + 8][k8 + tid4 + 4];
            }
            #pragma unroll
            for (int nb = 0; nb < 4; nb++) {
                int cn = wn*32 + nb*8 + gid;
                b[nb][0] = Wb[k8 + tid4    ][cn];
                b[nb][1] = Wb[k8 + tid4 + 4][cn];
            }
            #pragma unroll
            for (int ma = 0; ma < 4; ma++)
                #pragma unroll
                for (int nb = 0; nb < 4; nb++)
                    mma8(c[ma][nb], a[ma][0], a[ma][1], a[ma][2], a[ma][3],
                         b[nb][0], b[nb][1]);
        }
    };

    auto issue = [&](int kk, int buf) {
        #pragma unroll
        for (int v = 0; v < 4; v++) {            // A: 128x32
            int row = ar0 + 32*v;
            int gm  = m0 + row;
            const float* src = A + (long long)gm*K + kk + ac4*4;
            unsigned dst = (unsigned)__cvta_generic_to_shared(&As[buf][row][ac4*4]);
            asm volatile("cp.async.ca.shared.global [%0], [%1], 16, 16;"
                         :: "r"(dst), "l"(src));
        }
        #pragma unroll
        for (int v = 0; v < 4; v++) {            // W: 32x128
            int row = wr0 + 8*v;
            int gk  = kk + row;
            const float* src = W + (long long)gk*Nc + n0 + wc4*4;
            unsigned dst = (unsigned)__cvta_generic_to_shared(&Ws[buf][row][wc4*4]);
            asm volatile("cp.async.ca.shared.global [%0], [%1], 16, 16;"
                         :: "r"(dst), "l"(src));
        }
        asm volatile("cp.async.commit_group;");
    };

    int nb = K >> 5;
    issue(0, 0);
    int cur = 0;
    for (int cidx = 0; cidx < nb; cidx++) {
        asm volatile("cp.async.wait_group 0;" ::: "memory");
        __syncthreads();
        if (cidx + 1 < nb) issue((cidx+1) << 5, cur ^ 1);
        do_chunk(As[cur], Ws[cur]);
        cur ^= 1;
    }

    if (resMode == 4) {
        // gelu + segmented column sums, no C write. Reuse smem for partials.
        __syncthreads();
        float (*part)[16][132] = (float (*)[16][132])s_raw;
        const int g0 = (m0 - st*M2P) / CN;     // tile first-row group
        const int slot = wm*8 + gid;
        #pragma unroll
        for (int nb2 = 0; nb2 < 4; nb2++) {
            #pragma unroll
            for (int cc = 0; cc < 2; cc++) {
                int lcol = wn*32 + nb2*8 + 2*tid4 + cc;
                int gn = n0 + lcol;
                float s0 = 0.f, s1 = 0.f;
                #pragma unroll
                for (int ma = 0; ma < 4; ma++) {
                    #pragma unroll
                    for (int rr = 0; rr < 2; rr++) {
                        int gm = m0 + wm*64 + ma*16 + gid + rr*8;
                        int g2 = gm - st*M2P;
                        if (g2 >= CBPN) continue;
                        int grp = g2 / CN;
                        int nn  = g2 - grp*CN;
                        float v = c[ma][nb2][rr*2 + cc]
                                + res[((long long)(st*M1P + (grp/CP)*CN + nn))*Nc + gn];
                        v = 0.5f * v * (1.f + erff(v * 0.70710678118654752f));
                        if (grp == g0) s0 += v; else s1 += v;
                    }
                }
                part[0][slot][lcol] = s0;
                part[1][slot][lcol] = s1;
            }
        }
        __syncthreads();
        int lcol = t & 127, sg = t >> 7;
        float sum = 0.f;
        #pragma unroll
        for (int sl = 0; sl < 16; sl++) sum += part[sg][sl][lcol];
        g_hpart[((long long)by*2 + sg)*512 + n0 + lcol] = sum;
        return;
    }

    // ---- generic epilogue ----
    #pragma unroll
    for (int ma = 0; ma < 4; ma++) {
        #pragma unroll
        for (int rr = 0; rr < 2; rr++) {
            int gm = m0 + wm*64 + ma*16 + gid + rr*8;
            long long resBase = -1;
            int outRow = -1;
            if (resMode == 2) {
                int g2 = gm - st*M2P;
                if (g2 < CBPN) {
                    int bb = g2 / (CP * CN);
                    int nn = g2 % CN;
                    resBase = ((long long)(st*M1P + bb*CN + nn)) * Nc;
                }
            } else if (resMode == 3) {
                resBase = (long long)gm * Nc;
                int r_in = gm - st*mSplit;
                if (r_in < CBN) outRow = st*CBN + r_in;
            }
            if (resMode == 2 && resBase < 0) continue;  // pad row: skip
            #pragma unroll
            for (int nb2 = 0; nb2 < 4; nb2++) {
                #pragma unroll
                for (int cc = 0; cc < 2; cc++) {
                    int gn = n0 + wn*32 + nb2*8 + 2*tid4 + cc;
                    float v = c[ma][nb2][rr*2 + cc];
                    if (bias) v += bias[gn];
                    if (resMode == 3) {
                        float r = res[resBase + gn];
                        float xn = v + r;
                        if (outRow >= 0) C[(long long)outRow * Nc + gn] = xn;
                        proj[(long long)gm * Nc + gn] = xn - wv*r;
                        continue;
                    }
                    if (resMode == 2) v += res[resBase + gn];
                    if (act) v = 0.5f * v * (1.f + erff(v * 0.70710678118654752f));
                    C[(long long)gm * Nc + gn] = v;
                }
            }
        }
    }
}

// ---------------- prescale priors (both streams) ----------------
__global__ void k_prescale(const float* __restrict__ pri0, const float* __restrict__ pri1)
{
    long long idx = (long long)blockIdx.x*blockDim.x + threadIdx.x;
    if (idx >= (long long)2*CBPN*KPAD) return;
    int s = (int)(idx / ((long long)CBPN*KPAD));
    long long rem = idx - (long long)s*CBPN*KPAD;
    int k = (int)(rem % KPAD);
    long long rowc = rem / KPAD;
    const float* pri = s ? pri1 : pri0;
    float v = 0.f;
    if (k < CN) v = pri[rowc*CN + k] * g_invmass[s*CB*CP + (int)(rowc / CN)];
    g_pri_pad[((long long)s*M2P + rowc)*KPAD + k] = __uint_as_float(to_tf32(v));
}

__global__ void k_prep_pw(const float* __restrict__ pw)
{
    int idx = blockIdx.x*blockDim.x + threadIdx.x;
    if (idx >= KPAD*CH) return;
    int r = idx / CH, c = idx % CH;
    float v = (r < CN) ? pw[r*CH + c] : 0.f;
    g_pw_pad[idx] = __uint_as_float(to_tf32(v));
}

// ---------------- fused attention: 64-row i-tiles, 512 threads ----------------
// S[64][388] (A-frag banks 4*gid+tid4 ok), Ts[32][76] (B 12*gid+tid4 ok),
// Vs[32][72] (B 8*tid4+gid ok), Qs[64][68].
__global__ void __launch_bounds__(512) k_attn(const float* __restrict__ x0,
                                              const float* __restrict__ x1,
                                              const float* __restrict__ conn0,
                                              const float* __restrict__ conn1,
                                              const float* __restrict__ alpha)
{
    extern __shared__ unsigned char s_raw[];
    float (*S)[388]  = (float (*)[388])s_raw;
    float (*Qs)[68]  = (float (*)[68])(s_raw + 64*388*4);
    float (*Ts)[76]  = (float (*)[76])(s_raw + (64*388 + 64*68)*4);
    float (*Vs)[72]  = (float (*)[72])(s_raw + (64*388 + 64*68 + 32*76)*4);

    int blk = blockIdx.x;            // 2*CB*CNH*6
    int s = blk / (CB*48);
    int rem = blk % (CB*48);
    int b = rem / 48;
    int r2 = rem % 48;
    int h = r2 / 6;
    int i0 = (r2 % 6) * 64;
    int t = threadIdx.x;             // 0..511
    const float* x    = s ? x1 : x0;
    const float* conn = s ? conn1 : conn0;
    const long long qbase = (long long)s*M1P + (long long)b*CN;

    const int lane = t & 31, warp = t >> 5;   // 16 warps
    const int wm   = warp >> 2;      // 0..3  (m16 tiles -> 64 rows)
    const int wn   = warp & 3;       // 0..3
    const int gid  = lane >> 2;      // 0..7
    const int tid4 = lane & 3;       // 0..3
    const int qlr  = t >> 3;         // 0..63  Q loader row
    const int qlc  = (t & 7) * 8;    // Q loader col base
    const int klr  = t >> 4;         // 0..31  K/V loader row
    const int klc  = (t & 15) * 4;   // K/V loader col base

    // load Q tile 64x64
    {
        int gi = i0 + qlr;
        const float* src = g_qkv + (qbase + (gi < CN ? gi : 0))*3*CH + h*CHD + qlc;
        #pragma unroll
        for (int u = 0; u < 8; u++) Qs[qlr][qlc+u] = (gi < CN) ? src[u] : 0.f;
    }
    __syncthreads();

    // ---- phase 1: S = Q K^T (per 32-col chunk; warp (wm,wn) -> m16 x n8 tile) ----
    for (int j0 = 0; j0 < KPAD; j0 += 32) {
        {
            int gj = j0 + klr;
            const float* src = g_qkv + (qbase + (gj < CN ? gj : 0))*3*CH + CH + h*CHD + klc;
            #pragma unroll
            for (int u = 0; u < 4; u++) Ts[klr][klc+u] = (gj < CN) ? src[u] : 0.f;
        }
        __syncthreads();
        float c4[4] = {0.f,0.f,0.f,0.f};
        #pragma unroll
        for (int k8 = 0; k8 < 64; k8 += 8) {
            unsigned a0 = __float_as_uint(Qs[wm*16+gid  ][k8+tid4  ]);
            unsigned a1 = __float_as_uint(Qs[wm*16+gid+8][k8+tid4  ]);
            unsigned a2 = __float_as_uint(Qs[wm*16+gid  ][k8+tid4+4]);
            unsigned a3 = __float_as_uint(Qs[wm*16+gid+8][k8+tid4+4]);
            unsigned b0 = __float_as_uint(Ts[wn*8+gid][k8+tid4  ]);
            unsigned b1 = __float_as_uint(Ts[wn*8+gid][k8+tid4+4]);
            mma8(c4, a0, a1, a2, a3, b0, b1);
        }
        int col = j0 + wn*8 + 2*tid4;
        S[wm*16+gid  ][col  ] = c4[0];
        S[wm*16+gid  ][col+1] = c4[1];
        S[wm*16+gid+8][col  ] = c4[2];
        S[wm*16+gid+8][col+1] = c4[3];
        __syncthreads();
    }

    // ---- phase 2: inline mask + scale + row softmax (warp w: rows 4w..4w+3) ----
    {
        float a2c  = alpha[0]*0.5f;
        float base = a2c * g_msum[s*CB + b];
        float om   = 1.f - a2c;
        for (int rr = 0; rr < 4; rr++) {
            int i = warp*4 + rr;          // 0..63
            int gi = i0 + i;
            if (gi >= CN) continue;
            const float* crow = conn + (long long)gi*CN + (long long)b*CNN;
            float mx = -1e30f;
            for (int jc = lane; jc < CN; jc += 32) {
                float m = tanhf(base + om*crow[jc]);
                float v = 0.125f * S[i][jc] * (1.f + m);
                S[i][jc] = v;
                mx = fmaxf(mx, v);
            }
            #pragma unroll
            for (int o = 16; o > 0; o >>= 1) mx = fmaxf(mx, __shfl_xor_sync(~0u, mx, o));
            float sum = 0.f;
            for (int jc = lane; jc < CN; jc += 32) {
                float e = expf(S[i][jc] - mx);
                S[i][jc] = e;
                sum += e;
            }
            #pragma unroll
            for (int o = 16; o > 0; o >>= 1) sum += __shfl_xor_sync(~0u, sum, o);
            float inv = 1.f / sum;
            for (int jc = lane; jc < CN; jc += 32) S[i][jc] *= inv;
            for (int jc = CN + lane; jc < KPAD; jc += 32) S[i][jc] = 0.f;
        }
    }

    // ---- phase 3: ctx = P @ V (warp (wm,wn): rows wm*16, cols wn*16+16) ----
    float acc[2][4] = {};
    for (int j0 = 0; j0 < KPAD; j0 += 32) {
        __syncthreads();
        {
            int gj = j0 + klr;
            const float* src = g_qkv + (qbase + (gj < CN ? gj : 0))*3*CH + 2*CH + h*CHD + klc;
            #pragma unroll
            for (int u = 0; u < 4; u++) Vs[klr][klc+u] = (gj < CN) ? src[u] : 0.f;
        }
        __syncthreads();
        #pragma unroll
        for (int k8 = 0; k8 < 32; k8 += 8) {
            unsigned a0 = __float_as_uint(S[wm*16+gid  ][j0+k8+tid4  ]);
            unsigned a1 = __float_as_uint(S[wm*16+gid+8][j0+k8+tid4  ]);
            unsigned a2 = __float_as_uint(S[wm*16+gid  ][j0+k8+tid4+4]);
            unsigned a3 = __float_as_uint(S[wm*16+gid+8][j0+k8+tid4+4]);
            #pragma unroll
            for (int nt = 0; nt < 2; nt++) {
                int cn = wn*16 + nt*8 + gid;
                unsigned b0 = __float_as_uint(Vs[k8+tid4  ][cn]);
                unsigned b1 = __float_as_uint(Vs[k8+tid4+4][cn]);
                mma8(acc[nt], a0, a1, a2, a3, b0, b1);
            }
        }
    }
    // write: attnout = x + ctx + fn
    #pragma unroll
    for (int nt = 0; nt < 2; nt++) {
        #pragma unroll
        for (int rr = 0; rr < 2; rr++) {
            int gi = i0 + wm*16 + gid + rr*8;
            if (gi >= CN) continue;
            #pragma unroll
            for (int cc = 0; cc < 2; cc++) {
                int d = h*CHD + wn*16 + nt*8 + 2*tid4 + cc;
                long long oc = ((long long)(b*CN + gi))*CH + d;   // compact (x)
                long long op = (qbase + gi)*CH + d;                // padded
                g_attnout[op] = x[oc] + g_fn[op] + acc[nt][rr*2 + cc];
            }
        }
    }
}

// ---------------- layernorm (both streams; optional padded input) ----------------
__global__ void k_layernorm(const float* __restrict__ x0, const float* __restrict__ x1,
                            int inPadded, const float* __restrict__ g,
                            const float* __restrict__ b, int gRow0, float* __restrict__ z)
{
    int row = blockIdx.x;                 // 0..2*CBN-1
    int s = row >= CBN;
    int rin = row - s*CBN;
    const float* xr;
    if (inPadded) xr = x0 + ((long long)s*M1P + rin)*CH;
    else          xr = (s ? x1 : x0) + (long long)rin*CH;
    float* zr = z + ((long long)s*M1P + rin)*CH;
    const float* gp = g + (gRow0 + s)*CH;
    const float* bp = b + (gRow0 + s)*CH;
    __shared__ float red[256];
    int t = threadIdx.x;
    float v0 = xr[t], v1 = xr[t+256];
    red[t] = v0+v1; __syncthreads();
    for (int o=128;o>0;o>>=1){ if(t<o) red[t]+=red[t+o]; __syncthreads(); }
    float mean = red[0]*(1.f/CH); __syncthreads();
    float d0=v0-mean, d1=v1-mean;
    red[t]=d0*d0+d1*d1; __syncthreads();
    for (int o=128;o>0;o>>=1){ if(t<o) red[t]+=red[t+o]; __syncthreads(); }
    float rstd = rsqrtf(red[0]*(1.f/CH) + 1e-5f);
    zr[t]     = d0*rstd*gp[t]     + bp[t];
    zr[t+256] = d1*rstd*gp[t+256] + bp[t+256];
}

// ---------------- merged prior + conn reductions (conn read once) ----------------
__global__ void k_prior_all(const float* __restrict__ pri0, const float* __restrict__ pri1,
                            const float* __restrict__ conn0, const float* __restrict__ conn1)
{
    int blk = blockIdx.x;           // 2*CB*8
    int s = blk / (CB*8);
    int rem = blk % (CB*8);
    int b = rem >> 3, ch = rem & 7;
    const float* pri  = (s ? pri1 : pri0) + (long long)(b*CP)*CNN;
    const float* conn = (s ? conn1 : conn0) + (long long)b*CNN;
    const int CHK = (CNN + 7) / 8;
    int lo = ch*CHK, hi = lo + CHK; if (hi > CNN) hi = CNN;
    float acc[10] = {};   // dot0,q0,ab0, dot1,q1,ab1, dot2,q2,ab2, csq
    for (int i = lo + threadIdx.x; i < hi; i += blockDim.x) {
        float cv = conn[i];
        acc[9] += cv*cv;
        #pragma unroll
        for (int p = 0; p < CP; p++) {
            float pv = pri[(long long)p*CNN + i];
            acc[p*3+0] += pv*cv;
            acc[p*3+1] += pv*pv;
            acc[p*3+2] += fabsf(pv);
        }
    }
    __shared__ float red[10][256];
    int t = threadIdx.x;
    #pragma unroll
    for (int k = 0; k < 10; k++) red[k][t] = acc[k];
    __syncthreads();
    for (int o = 128; o > 0; o >>= 1) {
        if (t < o)
            #pragma unroll
            for (int k = 0; k < 10; k++) red[k][t] += red[k][t+o];
        __syncthreads();
    }
    if (t == 0) {
        #pragma unroll
        for (int p = 0; p < CP; p++) {
            int bp = (s*CB + b)*CP + p;
            g_dotp[bp*8+ch]  = red[p*3+0][0];
            g_psqp[bp*8+ch]  = red[p*3+1][0];
            g_pabsp[bp*8+ch] = red[p*3+2][0];
        }
        g_csqp[(s*CB+b)*8+ch] = red[9][0];
    }
}

__global__ void k_sw()
{
    if (threadIdx.x) return;
    int gb = blockIdx.x;            // 0..2*CB-1
    float csq=0;
    #pragma unroll
    for (int u=0;u<8;u++) csq += g_csqp[gb*8+u];
    float cn = fmaxf(sqrtf(csq), 1e-12f);
    float s[CP], mx=-1e30f;
    for (int p=0;p<CP;p++){
        int bp = gb*CP+p;
        float dot=0, sq=0, ab=0;
        #pragma unroll
        for (int u=0;u<8;u++){ dot+=g_dotp[bp*8+u]; sq+=g_psqp[bp*8+u]; ab+=g_pabsp[bp*8+u]; }
        float pn = fmaxf(sqrtf(sq), 1e-12f);
        s[p] = dot/(cn*pn);
        mx = fmaxf(mx, s[p]);
        g_invmass[bp] = 1.f/ab;
    }
    float sum=0;
    for (int p=0;p<CP;p++){ s[p]=expf(s[p]-mx); sum+=s[p]; }
    for (int p=0;p<CP;p++) g_sw[gb*CP+p]=s[p]/sum;
}

// ---------------- fused_nh (both streams) ----------------
__global__ void k_fused_nh()
{
    long long idx = (long long)blockIdx.x*blockDim.x + threadIdx.x;
    if (idx >= (long long)2*CBN*CH) return;
    int s = (int)(idx / X_SZ);
    long long rem = idx - (long long)s*X_SZ;
    int c = (int)(rem % CH);
    long long bn = rem / CH;
    int b = (int)(bn / CN), n = (int)(bn % CN);
    float acc=0;
    #pragma unroll
    for (int p=0;p<CP;p++)
        acc += g_sw[(s*CB+b)*CP+p] *
               g_pe[((long long)s*M2P + (long long)(b*CP+p)*CN + n)*CH + c];
    g_fn[((long long)s*M1P + bn)*CH + c] = acc;
}

// ---------------- gbar from per-tile segmented partials ----------------
__global__ void k_gbar_fin2()
{
    int gbp = blockIdx.x;           // 2*CB*CP
    int s = gbp / (CB*CP);
    int bp = gbp % (CB*CP);
    int c = threadIdx.x;            // 256
    int r0 = bp*CN, r1 = r0 + CN;
    int t0 = r0 >> 7, t1 = (r1-1) >> 7;
    float a0=0, a1=0;
    for (int byl = t0; byl <= t1; byl++){
        int g0t = (byl << 7) / CN;
        int seg = bp - g0t;         // 0 or 1
        const float* r = g_hpart + ((long long)((s*285 + byl)*2 + seg))*512;
        a0 += r[c]; a1 += r[c+256];
    }
    g_gbar[(s*MGP+bp)*CH+c]     = a0*(1.f/CN);
    g_gbar[(s*MGP+bp)*CH+c+256] = a1*(1.f/CN);
}

// ---------------- tiny weight-gen MHA (both streams) ----------------
__global__ void k_wg_attn(float* __restrict__ out)
{
    int gb = blockIdx.x;            // 0..2*CB-1
    int s = gb / CB;
    int b = gb % CB;
    __shared__ float logit[CWGH*CP*CP];
    int t = threadIdx.x;            // 64 threads
    if (t < CWGH*CP*CP) {
        int h = t/(CP*CP); int i = (t/CP)%CP; int j = t%CP;
        const float* q = g_qkvwg + (long long)(s*MGP + b*CP+i)*3*CH + h*128;
        const float* k = g_qkvwg + (long long)(s*MGP + b*CP+j)*3*CH + CH + h*128;
        float d=0;
        for (int x=0;x<128;x++) d += q[x]*k[x];
        logit[t] = d*0.08838834764831845f;   // 1/sqrt(128)
    }
    __syncthreads();
    if (t==0) {
        float aw[CP]={0,0,0};
        for (int h=0;h<CWGH;h++) for (int i=0;i<CP;i++) {
            float mx=-1e30f;
            for (int j=0;j<CP;j++) mx=fmaxf(mx, logit[(h*CP+i)*CP+j]);
            float e[CP], ss=0;
            for (int j=0;j<CP;j++){ e[j]=expf(logit[(h*CP+i)*CP+j]-mx); ss+=e[j]; }
            for (int j=0;j<CP;j++) aw[j]+= e[j]/ss;
        }
        for (int j=0;j<CP;j++) aw[j] *= (1.f/(CWGH*CP));
        float mx=-1e30f;
        for (int j=0;j<CP;j++) mx=fmaxf(mx, aw[j]);
        float ss=0, e[CP];
        for (int j=0;j<CP;j++){ e[j]=expf((aw[j]-mx)*100.f); ss+=e[j]; }  // temp 0.01
        float msum=0;
        float* awp = out + (s ? AWSC_OFF : AWFC_OFF) + b*CP;
        for (int j=0;j<CP;j++){ float a=e[j]/ss; awp[j]=a; msum+=a; }
        g_msum[gb]=msum;
    }
}

// ---------------- fused logsoftmax + KL (per row-pair) ----------------
__global__ void k_loss_all()
{
    int r = blockIdx.x;             // 0..CBN-1
    const float* p0 = g_proj + (long long)r*CH;
    const float* p1 = g_proj + ((long long)M1P + r)*CH;
    __shared__ float red[256];
    __shared__ double d1[256], d2[256];
    int t = threadIdx.x;
    float a0 = p0[t], b0 = p0[t+256];
    float a1 = p1[t], b1 = p1[t+256];

    red[t] = fmaxf(a0,b0); __syncthreads();
    for (int o=128;o>0;o>>=1){ if(t<o) red[t]=fmaxf(red[t],red[t+o]); __syncthreads(); }
    float mx0 = red[0]; __syncthreads();
    red[t] = expf(a0-mx0)+expf(b0-mx0); __syncthreads();
    for (int o=128;o>0;o>>=1){ if(t<o) red[t]+=red[t+o]; __syncthreads(); }
    float lse0 = logf(red[0]) + mx0; __syncthreads();
    red[t] = fmaxf(a1,b1); __syncthreads();
    for (int o=128;o>0;o>>=1){ if(t<o) red[t]=fmaxf(red[t],red[t+o]); __syncthreads(); }
    float mx1 = red[0]; __syncthreads();
    red[t] = expf(a1-mx1)+expf(b1-mx1); __syncthreads();
    for (int o=128;o>0;o>>=1){ if(t<o) red[t]+=red[t+o]; __syncthreads(); }
    float lse1 = logf(red[0]) + mx1; __syncthreads();

    float lf0 = a0 - lse0, lf1 = b0 - lse0;
    float ls0 = a1 - lse1, ls1 = b1 - lse1;
    d1[t] = (double)(expf(ls0)*(ls0-lf0)) + (double)(expf(ls1)*(ls1-lf1));
    d2[t] = (double)(expf(lf0)*(lf0-ls0)) + (double)(expf(lf1)*(lf1-ls1));
    __syncthreads();
    for (int o=128;o>0;o>>=1){ if(t<o){ d1[t]+=d1[t+o]; d2[t]+=d2[t+o]; } __syncthreads(); }
    if (t==0){ atomicAdd(&g_kl[0], d1[0]); atomicAdd(&g_kl[1], d2[0]); }
}

__global__ void k_zero_kl(){ g_kl[0]=0.0; g_kl[1]=0.0; }

__global__ void k_loss(float* __restrict__ out)
{
    out[0] = (float)(0.5*(g_kl[0]+g_kl[1])/(double)CBN);
}

// ---------------- host orchestration ----------------
// CRITICAL: __device__ symbols passed as kernel ARGUMENTS must be resolved via
// cudaGetSymbolAddress (host shadow address + GB300 ATS silently reads host RAM).
static float* sym_addr(const void* symbol)
{
    void* p = nullptr;
    cudaGetSymbolAddress(&p, symbol);
    return (float*)p;
}

extern "C" void kernel_launch(void* const* d_in, const int* in_sizes, int n_in,
                              void* d_out, int out_size)
{
    const float* x0      = (const float*)d_in[0];
    const float* x1      = (const float*)d_in[1];
    const float* pri0    = (const float*)d_in[2];
    const float* pri1    = (const float*)d_in[3];
    const float* conn0   = (const float*)d_in[4];
    const float* conn1   = (const float*)d_in[5];
    const float* dw      = (const float*)d_in[6];
    const float* wqkv0   = (const float*)d_in[7];
    const float* wqkv1   = (const float*)d_in[8];
    const float* ln_g    = (const float*)d_in[9];
    const float* ln_b    = (const float*)d_in[10];
    const float* ffn_w1  = (const float*)d_in[11];
    const float* ffn_b1  = (const float*)d_in[12];
    const float* ffn_w2  = (const float*)d_in[13];
    const float* ffn_b2  = (const float*)d_in[14];
    const float* pw      = (const float*)d_in[15];
    const float* pb      = (const float*)d_in[16];
    const float* f1w     = (const float*)d_in[17];
    const float* f1b     = (const float*)d_in[18];
    const float* f2w     = (const float*)d_in[19];
    const float* f2b     = (const float*)d_in[20];
    const float* ipw     = (const float*)d_in[21];
    const float* ipb     = (const float*)d_in[22];
    const float* alpha   = (const float*)d_in[23];
    float* out = (float*)d_out;

    float* p_z       = sym_addr(g_z);
    float* p_qkv     = sym_addr(g_qkv);
    float* p_pe      = sym_addr(g_pe);
    float* p_zc      = sym_addr(g_zc);
    float* p_attnout = sym_addr(g_attnout);
    float* p_ffnh    = sym_addr(g_ffnh);
    float* p_gbar    = sym_addr(g_gbar);
    float* p_tokens  = sym_addr(g_tokens);
    float* p_qkvwg   = sym_addr(g_qkvwg);
    float* p_proj    = sym_addr(g_proj);
    float* p_pri_pad = sym_addr(g_pri_pad);
    float* p_pw_pad  = sym_addr(g_pw_pad);

    cudaFuncSetAttribute(gemm_tc, cudaFuncAttributeMaxDynamicSharedMemorySize, GTC_SMEM);
    cudaFuncSetAttribute(k_attn,  cudaFuncAttributeMaxDynamicSharedMemorySize, ATT_SMEM);

    k_zero_kl<<<1,1>>>();
    k_prep_pw<<<(KPAD*CH+255)/256,256>>>(pw);

    // 1. pre-attention LN (both streams)
    k_layernorm<<<2*CBN,256>>>(x0, x1, 0, ln_g, ln_b, 0, p_z);
    // 2. QKV (both; per-stream weights)
    gemm_tc<<<12*190,256,GTC_SMEM>>>(p_z, wqkv0, wqkv1, nullptr, nullptr, p_qkv,
        2*M1P, CH, 3*CH, 12, M1P, nullptr, 0, 0, nullptr, nullptr);
    // 3. prior similarity + mass (merged conn/pri reductions)
    k_prior_all<<<2*CB*8,256>>>(pri0, pri1, conn0, conn1);
    k_sw<<<2*CB,32>>>();
    // 4. prescale priors then pe GEMM (shared weights)
    k_prescale<<<(int)(((long long)2*CBPN*KPAD+255)/256),256>>>(pri0, pri1);
    gemm_tc<<<4*570,256,GTC_SMEM>>>(p_pri_pad, p_pw_pad, p_pw_pad, pb, pb, p_pe,
        2*M2P, KPAD, CH, 4, M2P, nullptr, 0, 0, nullptr, nullptr);
    // 5. fused_nh
    k_fused_nh<<<(2*X_SZ+255)/256,256>>>();
    // 6. zc = z @ f1w[512:] + f1b (shared)
    gemm_tc<<<4*190,256,GTC_SMEM>>>(p_z, f1w + CH*CH, f1w + CH*CH, f1b, f1b, p_zc,
        2*M1P, CH, CH, 4, M1P, nullptr, 0, 0, nullptr, nullptr);
    // 7. gelu(pe @ f1w[:512] + zc) -> segmented column sums only (resMode 4)
    gemm_tc<<<4*570,256,GTC_SMEM>>>(p_pe, f1w, f1w, nullptr, nullptr, nullptr,
        2*M2P, CH, CH, 4, M2P, p_zc, 4, 1, nullptr, nullptr);
    // 8. gbar from partials ; tokens ; qkv_wg
    k_gbar_fin2<<<2*CB*CP,256>>>();
    gemm_tc<<<4*2,256,GTC_SMEM>>>(p_gbar, f2w, f2w, f2b, f2b, p_tokens,
        2*MGP, CH, CH, 4, MGP, nullptr, 0, 0, nullptr, nullptr);
    gemm_tc<<<12*2,256,GTC_SMEM>>>(p_tokens, ipw, ipw, ipb, ipb, p_qkvwg,
        2*MGP, CH, 3*CH, 12, MGP, nullptr, 0, 0, nullptr, nullptr);
    // 9. tiny MHA (writes aw_, msum)
    k_wg_attn<<<2*CB,64>>>(out);
    // 10. fused attention (tensor-core; 64-row tiles; inline mask)
    k_attn<<<2*CB*CNH*6,512,ATT_SMEM>>>(x0, x1, conn0, conn1, alpha);
    // 11. FFN (per-stream weights); ffn2 dual-writes out + proj
    k_layernorm<<<2*CBN,256>>>(p_attnout, nullptr, 1, ln_g, ln_b, 2, p_z);
    gemm_tc<<<16*190,256,GTC_SMEM>>>(p_z, ffn_w1, ffn_w1 + (long long)CH*4*CH,
        ffn_b1, ffn_b1 + 4*CH, p_ffnh,
        2*M1P, CH, 4*CH, 16, M1P, nullptr, 0, 1, nullptr, nullptr);
    gemm_tc<<<4*190,256,GTC_SMEM>>>(p_ffnh, ffn_w2, ffn_w2 + (long long)4*CH*CH,
        ffn_b2, ffn_b2 + CH, out,
        2*M1P, 4*CH, CH, 4, M1P, p_attnout, 3, 0, p_proj, dw);

    // distillation loss (fused logsoftmax + KL)
    k_loss_all<<<CBN,256>>>();
    k_loss<<<1,1>>>(out + LOSS_OFF);
}

// round 17
// speedup vs baseline: 1.0790x; 1.0111x over previous
#include <cuda_runtime.h>
#include <math.h>

// ---------------- problem constants ----------------
#define CB   32
#define CN   379
#define CH   512
#define CNH  8
#define CP   3
#define CWGH 4
#define CHD  64          // CH/CNH
#define CBN  (CB*CN)     // 12128
#define CBPN (CB*CP*CN)  // 36384
#define CNN  (CN*CN)     // 143641
#define KPAD 384         // pri K padded to multiple of 32

// padded per-stream row regions (multiples of 128)
#define M1P  12160       // 95*128  >= CBN
#define M2P  36480       // 285*128 >= CBPN  (285 tiles/stream)
#define MGP  128         // >= CB*CP

#define X_SZ   (CBN*CH)          // 6209536
#define LOSS_OFF (2*X_SZ)
#define AWFC_OFF (LOSS_OFF+1)
#define AWSC_OFF (AWFC_OFF + CB*CP)

// gemm_tc dynamic smem: 2 stages x (128x36 + 32x136) words
#define GTC_SMEM ((2*128*36 + 2*32*136)*4)          // 71680 B
// k_attn dynamic smem: S 64x388 + Q 64x68 + Ts 32x76 + Vs 32x72
#define ATT_SMEM ((64*388 + 64*68 + 32*76 + 32*72)*4)   // 135680 B

// ---------------- static scratch (two-stream padded layouts) ----------------
static __device__ float g_z[2*M1P*CH];
static __device__ float g_qkv[(long long)2*M1P*3*CH];
static __device__ float g_pe[(long long)2*M2P*CH];
static __device__ float g_zc[2*M1P*CH];
static __device__ float g_attnout[2*M1P*CH];
static __device__ float g_ffnh[(long long)2*M1P*4*CH];
static __device__ float g_proj[(long long)2*M1P*CH];
static __device__ float g_pri_pad[(long long)2*M2P*KPAD];
static __device__ float g_pw_pad[KPAD*CH];
static __device__ float g_hpart[570*2*512];     // per-tile segmented gelu column sums
static __device__ float g_gbar[2*MGP*CH];
static __device__ float g_tokens[2*MGP*CH];
static __device__ float g_qkvwg[2*MGP*3*CH];
static __device__ float g_dotp[2*CB*CP*8], g_psqp[2*CB*CP*8], g_pabsp[2*CB*CP*8];
static __device__ float g_csqp[2*CB*8];
static __device__ float g_sw[2*CB*CP], g_invmass[2*CB*CP], g_msum[2*CB];
static __device__ double g_kl[2];

__device__ __forceinline__ unsigned to_tf32(float v)
{
    unsigned r; asm("cvt.rna.tf32.f32 %0, %1;" : "=r"(r) : "f"(v)); return r;
}

__device__ __forceinline__ void mma8(float* c, unsigned a0, unsigned a1,
                                     unsigned a2, unsigned a3,
                                     unsigned b0, unsigned b1)
{
    asm volatile(
        "mma.sync.aligned.m16n8k8.row.col.f32.tf32.tf32.f32 "
        "{%0,%1,%2,%3}, {%4,%5,%6,%7}, {%8,%9}, {%0,%1,%2,%3};"
        : "+f"(c[0]), "+f"(c[1]), "+f"(c[2]), "+f"(c[3])
        : "r"(a0), "r"(a1), "r"(a2), "r"(a3), "r"(b0), "r"(b1));
}

// ---------------- tf32 tensor-core GEMM, dual-stream + dual-output ----------------
// Block tile 128x128, 256 threads = 8 warps (2m x 4n), warp tile 64x32,
// 2-stage cp.async, k-chunk 32, single barrier per chunk.
// m-side: st = (m0 >= mSplit) selects W1/b1 (per-stream weights).
// n-side: bx >= nSplit selects W2/b2 -> C2 with column stride Nc2 (shared weights,
//         secondary output). Pass nSplit = gridNx to disable.
// resMode: 0 none;
//          2: res[(st*M1P + b*CN + n)*ld + gn] with gm-st*M2P=(b*CP+p)*CN+n (skip pads);
//          3: res=attnout (padded); C=compact out row st*CBN+r_in (skip pads);
//             proj[gm*ld+gn] = xn - dwp[st]*res;
//          4: gelu(acc + res[mode2 addressing]); NO C write; per-tile segmented
//             column sums -> g_hpart[by*2+seg][n0+col].
__global__ void __launch_bounds__(256,2)
gemm_tc(const float* __restrict__ A,
        const float* __restrict__ W0, const float* __restrict__ W1,
        const float* __restrict__ b0, const float* __restrict__ b1,
        float* __restrict__ C,
        int M, int K, int Nc, int gridNx, int mSplit,
        const float* __restrict__ res, int resMode, int act,
        float* __restrict__ proj, const float* __restrict__ dwp,
        int nSplit, const float* __restrict__ W2, const float* __restrict__ b2,
        float* __restrict__ C2, int Nc2)
{
    extern __shared__ unsigned char s_raw[];
    unsigned (*As)[128][36] = (unsigned (*)[128][36])s_raw;
    unsigned (*Ws)[32][136] = (unsigned (*)[32][136])(s_raw + 2*128*36*4);

    const int t    = threadIdx.x;        // 0..255
    const int bx   = blockIdx.x % gridNx;
    const int by   = blockIdx.x / gridNx;
    const int m0   = by * 128;
    const int st   = (m0 >= mSplit) ? 1 : 0;

    const float* Wp; const float* biasp; float* Cp; int ldw, n0;
    if (bx < nSplit) {
        Wp = st ? W1 : W0; biasp = st ? b1 : b0; Cp = C; ldw = Nc;
        n0 = bx * 128;
    } else {
        Wp = W2; biasp = b2; Cp = C2; ldw = Nc2;
        n0 = (bx - nSplit) * 128;
    }

    const int lane = t & 31, warp = t >> 5;
    const int wm   = warp >> 2;          // 0..1
    const int wn   = warp & 3;           // 0..3
    const int gid  = lane >> 2;          // 0..7
    const int tid4 = lane & 3;           // 0..3

    const int ac4 = t & 7;
    const int ar0 = t >> 3;              // 0..31
    const int wc4 = t & 31;
    const int wr0 = t >> 5;              // 0..7

    const float wv = (resMode == 3) ? dwp[st] : 0.f;

    float c[4][4][4];
    #pragma unroll
    for (int i=0;i<4;i++)
        #pragma unroll
        for (int j=0;j<4;j++)
            #pragma unroll
            for (int k=0;k<4;k++) c[i][j][k]=0.f;

    auto do_chunk = [&](const unsigned (*Ab)[36], const unsigned (*Wb)[136]) {
        #pragma unroll
        for (int k8 = 0; k8 < 32; k8 += 8) {
            unsigned a[4][4], b[4][2];
            #pragma unroll
            for (int ma = 0; ma < 4; ma++) {
                int rb = wm*64 + ma*16;
                a[ma][0] = Ab[rb + gid    ][k8 + tid4    ];
                a[ma][1] = Ab[rb + gid + 8][k8 + tid4    ];
                a[ma][2] = Ab[rb + gid    ][k8 + tid4 + 4];
                a[ma][3] = Ab[rb + gid + 8][k8 + tid4 + 4];
            }
            #pragma unroll
            for (int nb = 0; nb < 4; nb++) {
                int cn = wn*32 + nb*8 + gid;
                b[nb][0] = Wb[k8 + tid4    ][cn];
                b[nb][1] = Wb[k8 + tid4 + 4][cn];
            }
            #pragma unroll
            for (int ma = 0; ma < 4; ma++)
                #pragma unroll
                for (int nb = 0; nb < 4; nb++)
                    mma8(c[ma][nb], a[ma][0], a[ma][1], a[ma][2], a[ma][3],
                         b[nb][0], b[nb][1]);
        }
    };

    auto issue = [&](int kk, int buf) {
        #pragma unroll
        for (int v = 0; v < 4; v++) {            // A: 128x32
            int row = ar0 + 32*v;
            int gm  = m0 + row;
            const float* src = A + (long long)gm*K + kk + ac4*4;
            unsigned dst = (unsigned)__cvta_generic_to_shared(&As[buf][row][ac4*4]);
            asm volatile("cp.async.ca.shared.global [%0], [%1], 16, 16;"
                         :: "r"(dst), "l"(src));
        }
        #pragma unroll
        for (int v = 0; v < 4; v++) {            // W: 32x128
            int row = wr0 + 8*v;
            int gk  = kk + row;
            const float* src = Wp + (long long)gk*ldw + n0 + wc4*4;
            unsigned dst = (unsigned)__cvta_generic_to_shared(&Ws[buf][row][wc4*4]);
            asm volatile("cp.async.ca.shared.global [%0], [%1], 16, 16;"
                         :: "r"(dst), "l"(src));
        }
        asm volatile("cp.async.commit_group;");
    };

    int nb = K >> 5;
    issue(0, 0);
    int cur = 0;
    for (int cidx = 0; cidx < nb; cidx++) {
        asm volatile("cp.async.wait_group 0;" ::: "memory");
        __syncthreads();
        if (cidx + 1 < nb) issue((cidx+1) << 5, cur ^ 1);
        do_chunk(As[cur], Ws[cur]);
        cur ^= 1;
    }

    if (resMode == 4) {
        // gelu + segmented column sums, no C write. Reuse smem for partials.
        __syncthreads();
        float (*part)[16][132] = (float (*)[16][132])s_raw;
        const int g0 = (m0 - st*M2P) / CN;     // tile first-row group
        const int slot = wm*8 + gid;
        #pragma unroll
        for (int nb2 = 0; nb2 < 4; nb2++) {
            #pragma unroll
            for (int cc = 0; cc < 2; cc++) {
                int lcol = wn*32 + nb2*8 + 2*tid4 + cc;
                int gn = n0 + lcol;
                float s0 = 0.f, s1 = 0.f;
                #pragma unroll
                for (int ma = 0; ma < 4; ma++) {
                    #pragma unroll
                    for (int rr = 0; rr < 2; rr++) {
                        int gm = m0 + wm*64 + ma*16 + gid + rr*8;
                        int g2 = gm - st*M2P;
                        if (g2 >= CBPN) continue;
                        int grp = g2 / CN;
                        int nn  = g2 - grp*CN;
                        float v = c[ma][nb2][rr*2 + cc]
                                + res[((long long)(st*M1P + (grp/CP)*CN + nn))*ldw + gn];
                        v = 0.5f * v * (1.f + erff(v * 0.70710678118654752f));
                        if (grp == g0) s0 += v; else s1 += v;
                    }
                }
                part[0][slot][lcol] = s0;
                part[1][slot][lcol] = s1;
            }
        }
        __syncthreads();
        int lcol = t & 127, sg = t >> 7;
        float sum = 0.f;
        #pragma unroll
        for (int sl = 0; sl < 16; sl++) sum += part[sg][sl][lcol];
        g_hpart[((long long)by*2 + sg)*512 + n0 + lcol] = sum;
        return;
    }

    // ---- generic epilogue ----
    #pragma unroll
    for (int ma = 0; ma < 4; ma++) {
        #pragma unroll
        for (int rr = 0; rr < 2; rr++) {
            int gm = m0 + wm*64 + ma*16 + gid + rr*8;
            long long resBase = -1;
            int outRow = -1;
            if (resMode == 2) {
                int g2 = gm - st*M2P;
                if (g2 < CBPN) {
                    int bb = g2 / (CP * CN);
                    int nn = g2 % CN;
                    resBase = ((long long)(st*M1P + bb*CN + nn)) * ldw;
                }
            } else if (resMode == 3) {
                resBase = (long long)gm * ldw;
                int r_in = gm - st*mSplit;
                if (r_in < CBN) outRow = st*CBN + r_in;
            }
            if (resMode == 2 && resBase < 0) continue;  // pad row: skip
            #pragma unroll
            for (int nb2 = 0; nb2 < 4; nb2++) {
                #pragma unroll
                for (int cc = 0; cc < 2; cc++) {
                    int gn = n0 + wn*32 + nb2*8 + 2*tid4 + cc;
                    float v = c[ma][nb2][rr*2 + cc];
                    if (biasp) v += biasp[gn];
                    if (resMode == 3) {
                        float r = res[resBase + gn];
                        float xn = v + r;
                        if (outRow >= 0) Cp[(long long)outRow * ldw + gn] = xn;
                        proj[(long long)gm * ldw + gn] = xn - wv*r;
                        continue;
                    }
                    if (resMode == 2) v += res[resBase + gn];
                    if (act) v = 0.5f * v * (1.f + erff(v * 0.70710678118654752f));
                    Cp[(long long)gm * ldw + gn] = v;
                }
            }
        }
    }
}

// ---------------- prescale priors (both streams) ----------------
__global__ void k_prescale(const float* __restrict__ pri0, const float* __restrict__ pri1)
{
    long long idx = (long long)blockIdx.x*blockDim.x + threadIdx.x;
    if (idx >= (long long)2*CBPN*KPAD) return;
    int s = (int)(idx / ((long long)CBPN*KPAD));
    long long rem = idx - (long long)s*CBPN*KPAD;
    int k = (int)(rem % KPAD);
    long long rowc = rem / KPAD;
    const float* pri = s ? pri1 : pri0;
    float v = 0.f;
    if (k < CN) v = pri[rowc*CN + k] * g_invmass[s*CB*CP + (int)(rowc / CN)];
    g_pri_pad[((long long)s*M2P + rowc)*KPAD + k] = __uint_as_float(to_tf32(v));
}

__global__ void k_prep_pw(const float* __restrict__ pw)
{
    int idx = blockIdx.x*blockDim.x + threadIdx.x;
    if (idx >= KPAD*CH) return;
    int r = idx / CH, c = idx % CH;
    float v = (r < CN) ? pw[r*CH + c] : 0.f;
    g_pw_pad[idx] = __uint_as_float(to_tf32(v));
}

// ---------------- fused attention: 64-row i-tiles, 512 threads, inline mask+fn ----
__global__ void __launch_bounds__(512) k_attn(const float* __restrict__ x0,
                                              const float* __restrict__ x1,
                                              const float* __restrict__ conn0,
                                              const float* __restrict__ conn1,
                                              const float* __restrict__ alpha)
{
    extern __shared__ unsigned char s_raw[];
    float (*S)[388]  = (float (*)[388])s_raw;
    float (*Qs)[68]  = (float (*)[68])(s_raw + 64*388*4);
    float (*Ts)[76]  = (float (*)[76])(s_raw + (64*388 + 64*68)*4);
    float (*Vs)[72]  = (float (*)[72])(s_raw + (64*388 + 64*68 + 32*76)*4);

    int blk = blockIdx.x;            // 2*CB*CNH*6
    int s = blk / (CB*48);
    int rem = blk % (CB*48);
    int b = rem / 48;
    int r2 = rem % 48;
    int h = r2 / 6;
    int i0 = (r2 % 6) * 64;
    int t = threadIdx.x;             // 0..511
    const float* x    = s ? x1 : x0;
    const float* conn = s ? conn1 : conn0;
    const long long qbase = (long long)s*M1P + (long long)b*CN;

    const int lane = t & 31, warp = t >> 5;   // 16 warps
    const int wm   = warp >> 2;      // 0..3
    const int wn   = warp & 3;       // 0..3
    const int gid  = lane >> 2;      // 0..7
    const int tid4 = lane & 3;       // 0..3
    const int qlr  = t >> 3;         // 0..63
    const int qlc  = (t & 7) * 8;
    const int klr  = t >> 4;         // 0..31
    const int klc  = (t & 15) * 4;

    const float sw0 = g_sw[(s*CB+b)*CP+0];
    const float sw1 = g_sw[(s*CB+b)*CP+1];
    const float sw2 = g_sw[(s*CB+b)*CP+2];

    // load Q tile 64x64
    {
        int gi = i0 + qlr;
        const float* src = g_qkv + (qbase + (gi < CN ? gi : 0))*3*CH + h*CHD + qlc;
        #pragma unroll
        for (int u = 0; u < 8; u++) Qs[qlr][qlc+u] = (gi < CN) ? src[u] : 0.f;
    }
    __syncthreads();

    // ---- phase 1: S = Q K^T ----
    for (int j0 = 0; j0 < KPAD; j0 += 32) {
        {
            int gj = j0 + klr;
            const float* src = g_qkv + (qbase + (gj < CN ? gj : 0))*3*CH + CH + h*CHD + klc;
            #pragma unroll
            for (int u = 0; u < 4; u++) Ts[klr][klc+u] = (gj < CN) ? src[u] : 0.f;
        }
        __syncthreads();
        float c4[4] = {0.f,0.f,0.f,0.f};
        #pragma unroll
        for (int k8 = 0; k8 < 64; k8 += 8) {
            unsigned a0 = __float_as_uint(Qs[wm*16+gid  ][k8+tid4  ]);
            unsigned a1 = __float_as_uint(Qs[wm*16+gid+8][k8+tid4  ]);
            unsigned a2 = __float_as_uint(Qs[wm*16+gid  ][k8+tid4+4]);
            unsigned a3 = __float_as_uint(Qs[wm*16+gid+8][k8+tid4+4]);
            unsigned b0 = __float_as_uint(Ts[wn*8+gid][k8+tid4  ]);
            unsigned b1 = __float_as_uint(Ts[wn*8+gid][k8+tid4+4]);
            mma8(c4, a0, a1, a2, a3, b0, b1);
        }
        int col = j0 + wn*8 + 2*tid4;
        S[wm*16+gid  ][col  ] = c4[0];
        S[wm*16+gid  ][col+1] = c4[1];
        S[wm*16+gid+8][col  ] = c4[2];
        S[wm*16+gid+8][col+1] = c4[3];
        __syncthreads();
    }

    // ---- phase 2: inline mask + scale + row softmax (warp w: rows 4w..4w+3) ----
    {
        float a2c  = alpha[0]*0.5f;
        float base = a2c * g_msum[s*CB + b];
        float om   = 1.f - a2c;
        for (int rr = 0; rr < 4; rr++) {
            int i = warp*4 + rr;          // 0..63
            int gi = i0 + i;
            if (gi >= CN) continue;
            const float* crow = conn + (long long)gi*CN + (long long)b*CNN;
            float mx = -1e30f;
            for (int jc = lane; jc < CN; jc += 32) {
                float m = tanhf(base + om*crow[jc]);
                float v = 0.125f * S[i][jc] * (1.f + m);
                S[i][jc] = v;
                mx = fmaxf(mx, v);
            }
            #pragma unroll
            for (int o = 16; o > 0; o >>= 1) mx = fmaxf(mx, __shfl_xor_sync(~0u, mx, o));
            float sum = 0.f;
            for (int jc = lane; jc < CN; jc += 32) {
                float e = expf(S[i][jc] - mx);
                S[i][jc] = e;
                sum += e;
            }
            #pragma unroll
            for (int o = 16; o > 0; o >>= 1) sum += __shfl_xor_sync(~0u, sum, o);
            float inv = 1.f / sum;
            for (int jc = lane; jc < CN; jc += 32) S[i][jc] *= inv;
            for (int jc = CN + lane; jc < KPAD; jc += 32) S[i][jc] = 0.f;
        }
    }

    // ---- phase 3: ctx = P @ V ----
    float acc[2][4] = {};
    for (int j0 = 0; j0 < KPAD; j0 += 32) {
        __syncthreads();
        {
            int gj = j0 + klr;
            const float* src = g_qkv + (qbase + (gj < CN ? gj : 0))*3*CH + 2*CH + h*CHD + klc;
            #pragma unroll
            for (int u = 0; u < 4; u++) Vs[klr][klc+u] = (gj < CN) ? src[u] : 0.f;
        }
        __syncthreads();
        #pragma unroll
        for (int k8 = 0; k8 < 32; k8 += 8) {
            unsigned a0 = __float_as_uint(S[wm*16+gid  ][j0+k8+tid4  ]);
            unsigned a1 = __float_as_uint(S[wm*16+gid+8][j0+k8+tid4  ]);
            unsigned a2 = __float_as_uint(S[wm*16+gid  ][j0+k8+tid4+4]);
            unsigned a3 = __float_as_uint(S[wm*16+gid+8][j0+k8+tid4+4]);
            #pragma unroll
            for (int nt = 0; nt < 2; nt++) {
                int cn = wn*16 + nt*8 + gid;
                unsigned b0 = __float_as_uint(Vs[k8+tid4  ][cn]);
                unsigned b1 = __float_as_uint(Vs[k8+tid4+4][cn]);
                mma8(acc[nt], a0, a1, a2, a3, b0, b1);
            }
        }
    }
    // write: attnout = x + fn + ctx  (fn = sum_p sw_p * pe[b,p,gi,d], inline)
    #pragma unroll
    for (int nt = 0; nt < 2; nt++) {
        #pragma unroll
        for (int rr = 0; rr < 2; rr++) {
            int gi = i0 + wm*16 + gid + rr*8;
            if (gi >= CN) continue;
            const float* pe0 = g_pe + ((long long)s*M2P + (long long)(b*CP+0)*CN + gi)*CH;
            const float* pe1 = g_pe + ((long long)s*M2P + (long long)(b*CP+1)*CN + gi)*CH;
            const float* pe2 = g_pe + ((long long)s*M2P + (long long)(b*CP+2)*CN + gi)*CH;
            #pragma unroll
            for (int cc = 0; cc < 2; cc++) {
                int d = h*CHD + wn*16 + nt*8 + 2*tid4 + cc;
                float fnv = sw0*pe0[d] + sw1*pe1[d] + sw2*pe2[d];
                long long oc = ((long long)(b*CN + gi))*CH + d;   // compact (x)
                long long op = (qbase + gi)*CH + d;                // padded
                g_attnout[op] = x[oc] + fnv + acc[nt][rr*2 + cc];
            }
        }
    }
}

// ---------------- layernorm (both streams; optional padded input) ----------------
__global__ void k_layernorm(const float* __restrict__ x0, const float* __restrict__ x1,
                            int inPadded, const float* __restrict__ g,
                            const float* __restrict__ b, int gRow0, float* __restrict__ z)
{
    int row = blockIdx.x;                 // 0..2*CBN-1
    int s = row >= CBN;
    int rin = row - s*CBN;
    const float* xr;
    if (inPadded) xr = x0 + ((long long)s*M1P + rin)*CH;
    else          xr = (s ? x1 : x0) + (long long)rin*CH;
    float* zr = z + ((long long)s*M1P + rin)*CH;
    const float* gp = g + (gRow0 + s)*CH;
    const float* bp = b + (gRow0 + s)*CH;
    __shared__ float red[256];
    int t = threadIdx.x;
    float v0 = xr[t], v1 = xr[t+256];
    red[t] = v0+v1; __syncthreads();
    for (int o=128;o>0;o>>=1){ if(t<o) red[t]+=red[t+o]; __syncthreads(); }
    float mean = red[0]*(1.f/CH); __syncthreads();
    float d0=v0-mean, d1=v1-mean;
    red[t]=d0*d0+d1*d1; __syncthreads();
    for (int o=128;o>0;o>>=1){ if(t<o) red[t]+=red[t+o]; __syncthreads(); }
    float rstd = rsqrtf(red[0]*(1.f/CH) + 1e-5f);
    zr[t]     = d0*rstd*gp[t]     + bp[t];
    zr[t+256] = d1*rstd*gp[t+256] + bp[t+256];
}

// ---------------- merged prior + conn reductions (conn read once) ----------------
__global__ void k_prior_all(const float* __restrict__ pri0, const float* __restrict__ pri1,
                            const float* __restrict__ conn0, const float* __restrict__ conn1)
{
    int blk = blockIdx.x;           // 2*CB*8
    int s = blk / (CB*8);
    int rem = blk % (CB*8);
    int b = rem >> 3, ch = rem & 7;
    const float* pri  = (s ? pri1 : pri0) + (long long)(b*CP)*CNN;
    const float* conn = (s ? conn1 : conn0) + (long long)b*CNN;
    const int CHK = (CNN + 7) / 8;
    int lo = ch*CHK, hi = lo + CHK; if (hi > CNN) hi = CNN;
    float acc[10] = {};   // dot0,q0,ab0, dot1,q1,ab1, dot2,q2,ab2, csq
    for (int i = lo + threadIdx.x; i < hi; i += blockDim.x) {
        float cv = conn[i];
        acc[9] += cv*cv;
        #pragma unroll
        for (int p = 0; p < CP; p++) {
            float pv = pri[(long long)p*CNN + i];
            acc[p*3+0] += pv*cv;
            acc[p*3+1] += pv*pv;
            acc[p*3+2] += fabsf(pv);
        }
    }
    __shared__ float red[10][256];
    int t = threadIdx.x;
    #pragma unroll
    for (int k = 0; k < 10; k++) red[k][t] = acc[k];
    __syncthreads();
    for (int o = 128; o > 0; o >>= 1) {
        if (t < o)
            #pragma unroll
            for (int k = 0; k < 10; k++) red[k][t] += red[k][t+o];
        __syncthreads();
    }
    if (t == 0) {
        #pragma unroll
        for (int p = 0; p < CP; p++) {
            int bp = (s*CB + b)*CP + p;
            g_dotp[bp*8+ch]  = red[p*3+0][0];
            g_psqp[bp*8+ch]  = red[p*3+1][0];
            g_pabsp[bp*8+ch] = red[p*3+2][0];
        }
        g_csqp[(s*CB+b)*8+ch] = red[9][0];
    }
}

__global__ void k_sw()
{
    if (threadIdx.x) return;
    int gb = blockIdx.x;            // 0..2*CB-1
    float csq=0;
    #pragma unroll
    for (int u=0;u<8;u++) csq += g_csqp[gb*8+u];
    float cn = fmaxf(sqrtf(csq), 1e-12f);
    float s[CP], mx=-1e30f;
    for (int p=0;p<CP;p++){
        int bp = gb*CP+p;
        float dot=0, sq=0, ab=0;
        #pragma unroll
        for (int u=0;u<8;u++){ dot+=g_dotp[bp*8+u]; sq+=g_psqp[bp*8+u]; ab+=g_pabsp[bp*8+u]; }
        float pn = fmaxf(sqrtf(sq), 1e-12f);
        s[p] = dot/(cn*pn);
        mx = fmaxf(mx, s[p]);
        g_invmass[bp] = 1.f/ab;
    }
    float sum=0;
    for (int p=0;p<CP;p++){ s[p]=expf(s[p]-mx); sum+=s[p]; }
    for (int p=0;p<CP;p++) g_sw[gb*CP+p]=s[p]/sum;
}

// ---------------- gbar from per-tile segmented partials ----------------
__global__ void k_gbar_fin2()
{
    int gbp = blockIdx.x;           // 2*CB*CP
    int s = gbp / (CB*CP);
    int bp = gbp % (CB*CP);
    int c = threadIdx.x;            // 256
    int r0 = bp*CN, r1 = r0 + CN;
    int t0 = r0 >> 7, t1 = (r1-1) >> 7;
    float a0=0, a1=0;
    for (int byl = t0; byl <= t1; byl++){
        int g0t = (byl << 7) / CN;
        int seg = bp - g0t;         // 0 or 1
        const float* r = g_hpart + ((long long)((s*285 + byl)*2 + seg))*512;
        a0 += r[c]; a1 += r[c+256];
    }
    g_gbar[(s*MGP+bp)*CH+c]     = a0*(1.f/CN);
    g_gbar[(s*MGP+bp)*CH+c+256] = a1*(1.f/CN);
}

// ---------------- tiny weight-gen MHA (both streams) ----------------
__global__ void k_wg_attn(float* __restrict__ out)
{
    int gb = blockIdx.x;            // 0..2*CB-1
    int s = gb / CB;
    int b = gb % CB;
    __shared__ float logit[CWGH*CP*CP];
    int t = threadIdx.x;            // 64 threads
    if (t < CWGH*CP*CP) {
        int h = t/(CP*CP); int i = (t/CP)%CP; int j = t%CP;
        const float* q = g_qkvwg + (long long)(s*MGP + b*CP+i)*3*CH + h*128;
        const float* k = g_qkvwg + (long long)(s*MGP + b*CP+j)*3*CH + CH + h*128;
        float d=0;
        for (int x=0;x<128;x++) d += q[x]*k[x];
        logit[t] = d*0.08838834764831845f;   // 1/sqrt(128)
    }
    __syncthreads();
    if (t==0) {
        float aw[CP]={0,0,0};
        for (int h=0;h<CWGH;h++) for (int i=0;i<CP;i++) {
            float mx=-1e30f;
            for (int j=0;j<CP;j++) mx=fmaxf(mx, logit[(h*CP+i)*CP+j]);
            float e[CP], ss=0;
            for (int j=0;j<CP;j++){ e[j]=expf(logit[(h*CP+i)*CP+j]-mx); ss+=e[j]; }
            for (int j=0;j<CP;j++) aw[j]+= e[j]/ss;
        }
        for (int j=0;j<CP;j++) aw[j] *= (1.f/(CWGH*CP));
        float mx=-1e30f;
        for (int j=0;j<CP;j++) mx=fmaxf(mx, aw[j]);
        float ss=0, e[CP];
        for (int j=0;j<CP;j++){ e[j]=expf((aw[j]-mx)*100.f); ss+=e[j]; }  // temp 0.01
        float msum=0;
        float* awp = out + (s ? AWSC_OFF : AWFC_OFF) + b*CP;
        for (int j=0;j<CP;j++){ float a=e[j]/ss; awp[j]=a; msum+=a; }
        g_msum[gb]=msum;
    }
}

// ---------------- fused logsoftmax + KL (per row-pair) ----------------
__global__ void k_loss_all()
{
    int r = blockIdx.x;             // 0..CBN-1
    const float* p0 = g_proj + (long long)r*CH;
    const float* p1 = g_proj + ((long long)M1P + r)*CH;
    __shared__ float red[256];
    __shared__ double d1[256], d2[256];
    int t = threadIdx.x;
    float a0 = p0[t], b0 = p0[t+256];
    float a1 = p1[t], b1 = p1[t+256];

    red[t] = fmaxf(a0,b0); __syncthreads();
    for (int o=128;o>0;o>>=1){ if(t<o) red[t]=fmaxf(red[t],red[t+o]); __syncthreads(); }
    float mx0 = red[0]; __syncthreads();
    red[t] = expf(a0-mx0)+expf(b0-mx0); __syncthreads();
    for (int o=128;o>0;o>>=1){ if(t<o) red[t]+=red[t+o]; __syncthreads(); }
    float lse0 = logf(red[0]) + mx0; __syncthreads();
    red[t] = fmaxf(a1,b1); __syncthreads();
    for (int o=128;o>0;o>>=1){ if(t<o) red[t]=fmaxf(red[t],red[t+o]); __syncthreads(); }
    float mx1 = red[0]; __syncthreads();
    red[t] = expf(a1-mx1)+expf(b1-mx1); __syncthreads();
    for (int o=128;o>0;o>>=1){ if(t<o) red[t]+=red[t+o]; __syncthreads(); }
    float lse1 = logf(red[0]) + mx1; __syncthreads();

    float lf0 = a0 - lse0, lf1 = b0 - lse0;
    float ls0 = a1 - lse1, ls1 = b1 - lse1;
    d1[t] = (double)(expf(ls0)*(ls0-lf0)) + (double)(expf(ls1)*(ls1-lf1));
    d2[t] = (double)(expf(lf0)*(lf0-ls0)) + (double)(expf(lf1)*(lf1-ls1));
    __syncthreads();
    for (int o=128;o>0;o>>=1){ if(t<o){ d1[t]+=d1[t+o]; d2[t]+=d2[t+o]; } __syncthreads(); }
    if (t==0){ atomicAdd(&g_kl[0], d1[0]); atomicAdd(&g_kl[1], d2[0]); }
}

__global__ void k_zero_kl(){ g_kl[0]=0.0; g_kl[1]=0.0; }

__global__ void k_loss(float* __restrict__ out)
{
    out[0] = (float)(0.5*(g_kl[0]+g_kl[1])/(double)CBN);
}

// ---------------- host orchestration ----------------
// CRITICAL: __device__ symbols passed as kernel ARGUMENTS must be resolved via
// cudaGetSymbolAddress (host shadow address + GB300 ATS silently reads host RAM).
static float* sym_addr(const void* symbol)
{
    void* p = nullptr;
    cudaGetSymbolAddress(&p, symbol);
    return (float*)p;
}

extern "C" void kernel_launch(void* const* d_in, const int* in_sizes, int n_in,
                              void* d_out, int out_size)
{
    const float* x0      = (const float*)d_in[0];
    const float* x1      = (const float*)d_in[1];
    const float* pri0    = (const float*)d_in[2];
    const float* pri1    = (const float*)d_in[3];
    const float* conn0   = (const float*)d_in[4];
    const float* conn1   = (const float*)d_in[5];
    const float* dw      = (const float*)d_in[6];
    const float* wqkv0   = (const float*)d_in[7];
    const float* wqkv1   = (const float*)d_in[8];
    const float* ln_g    = (const float*)d_in[9];
    const float* ln_b    = (const float*)d_in[10];
    const float* ffn_w1  = (const float*)d_in[11];
    const float* ffn_b1  = (const float*)d_in[12];
    const float* ffn_w2  = (const float*)d_in[13];
    const float* ffn_b2  = (const float*)d_in[14];
    const float* pw      = (const float*)d_in[15];
    const float* pb      = (const float*)d_in[16];
    const float* f1w     = (const float*)d_in[17];
    const float* f1b     = (const float*)d_in[18];
    const float* f2w     = (const float*)d_in[19];
    const float* f2b     = (const float*)d_in[20];
    const float* ipw     = (const float*)d_in[21];
    const float* ipb     = (const float*)d_in[22];
    const float* alpha   = (const float*)d_in[23];
    float* out = (float*)d_out;

    float* p_z       = sym_addr(g_z);
    float* p_qkv     = sym_addr(g_qkv);
    float* p_pe      = sym_addr(g_pe);
    float* p_zc      = sym_addr(g_zc);
    float* p_attnout = sym_addr(g_attnout);
    float* p_ffnh    = sym_addr(g_ffnh);
    float* p_gbar    = sym_addr(g_gbar);
    float* p_tokens  = sym_addr(g_tokens);
    float* p_qkvwg   = sym_addr(g_qkvwg);
    float* p_proj    = sym_addr(g_proj);
    float* p_pri_pad = sym_addr(g_pri_pad);
    float* p_pw_pad  = sym_addr(g_pw_pad);

    cudaFuncSetAttribute(gemm_tc, cudaFuncAttributeMaxDynamicSharedMemorySize, GTC_SMEM);
    cudaFuncSetAttribute(k_attn,  cudaFuncAttributeMaxDynamicSharedMemorySize, ATT_SMEM);

    k_zero_kl<<<1,1>>>();
    k_prep_pw<<<(KPAD*CH+255)/256,256>>>(pw);

    // 1. pre-attention LN (both streams)
    k_layernorm<<<2*CBN,256>>>(x0, x1, 0, ln_g, ln_b, 0, p_z);
    // 2. QKV + zc merged (n-split: 12 blocks QKV per-stream, 4 blocks zc shared)
    gemm_tc<<<16*190,256,GTC_SMEM>>>(p_z, wqkv0, wqkv1, nullptr, nullptr, p_qkv,
        2*M1P, CH, 3*CH, 16, M1P, nullptr, 0, 0, nullptr, nullptr,
        12, f1w + CH*CH, f1b, p_zc, CH);
    // 3. prior similarity + mass (merged conn/pri reductions)
    k_prior_all<<<2*CB*8,256>>>(pri0, pri1, conn0, conn1);
    k_sw<<<2*CB,32>>>();
    // 4. prescale priors then pe GEMM (shared weights)
    k_prescale<<<(int)(((long long)2*CBPN*KPAD+255)/256),256>>>(pri0, pri1);
    gemm_tc<<<4*570,256,GTC_SMEM>>>(p_pri_pad, p_pw_pad, p_pw_pad, pb, pb, p_pe,
        2*M2P, KPAD, CH, 4, M2P, nullptr, 0, 0, nullptr, nullptr,
        4, nullptr, nullptr, nullptr, 0);
    // 5. gelu(pe @ f1w[:512] + zc) -> segmented column sums only (resMode 4)
    gemm_tc<<<4*570,256,GTC_SMEM>>>(p_pe, f1w, f1w, nullptr, nullptr, nullptr,
        2*M2P, CH, CH, 4, M2P, p_zc, 4, 1, nullptr, nullptr,
        4, nullptr, nullptr, nullptr, 0);
    // 6. gbar from partials ; tokens ; qkv_wg
    k_gbar_fin2<<<2*CB*CP,256>>>();
    gemm_tc<<<4*2,256,GTC_SMEM>>>(p_gbar, f2w, f2w, f2b, f2b, p_tokens,
        2*MGP, CH, CH, 4, MGP, nullptr, 0, 0, nullptr, nullptr,
        4, nullptr, nullptr, nullptr, 0);
    gemm_tc<<<12*2,256,GTC_SMEM>>>(p_tokens, ipw, ipw, ipb, ipb, p_qkvwg,
        2*MGP, CH, 3*CH, 12, MGP, nullptr, 0, 0, nullptr, nullptr,
        12, nullptr, nullptr, nullptr, 0);
    // 7. tiny MHA (writes aw_, msum)
    k_wg_attn<<<2*CB,64>>>(out);
    // 8. fused attention (tensor-core; 64-row tiles; inline mask + inline fn)
    k_attn<<<2*CB*CNH*6,512,ATT_SMEM>>>(x0, x1, conn0, conn1, alpha);
    // 9. FFN (per-stream weights); ffn2 dual-writes out + proj
    k_layernorm<<<2*CBN,256>>>(p_attnout, nullptr, 1, ln_g, ln_b, 2, p_z);
    gemm_tc<<<16*190,256,GTC_SMEM>>>(p_z, ffn_w1, ffn_w1 + (long long)CH*4*CH,
        ffn_b1, ffn_b1 + 4*CH, p_ffnh,
        2*M1P, CH, 4*CH, 16, M1P, nullptr, 0, 1, nullptr, nullptr,
        16, nullptr, nullptr, nullptr, 0);
    gemm_tc<<<4*190,256,GTC_SMEM>>>(p_ffnh, ffn_w2, ffn_w2 + (long long)4*CH*CH,
        ffn_b2, ffn_b2 + CH, out,
        2*M1P, 4*CH, CH, 4, M1P, p_attnout, 3, 0, p_proj, dw,
        4, nullptr, nullptr, nullptr, 0);

    // distillation loss (fused logsoftmax + KL)
    k_loss_all<<<CBN,256>>>();
    k_loss<<<1,1>>>(out + LOSS_OFF);
}